// round 1
// baseline (speedup 1.0000x reference)
#include <cuda_runtime.h>
#include <cmath>

// Problem constants
#define B_   8
#define T_   2048
#define C_   1024
#define M_   (B_*T_)       // 16384
#define BTC  (B_*T_*C_)    // 16777216

// Scratch (no cudaMalloc allowed) — 6 x 64MB fp32 buffers + small z
__device__ float g_xk[BTC];
__device__ float g_xv[BTC];
__device__ float g_xr[BTC];
__device__ float g_k[BTC];
__device__ float g_v[BTC];
__device__ float g_r[BTC];
__device__ float g_z[B_*C_];

// ---------------------------------------------------------------------------
// K1: embedding gather + time-mix -> xk, xv, xr  [B*T, C]
// ---------------------------------------------------------------------------
__global__ __launch_bounds__(256)
void embed_mix_kernel(const int*   __restrict__ tok,
                      const float* __restrict__ xx_init,
                      const float* __restrict__ emb,
                      const float* __restrict__ tmk,
                      const float* __restrict__ tmv,
                      const float* __restrict__ tmr)
{
    int idx = blockIdx.x * blockDim.x + threadIdx.x;   // < BTC
    int c  = idx & (C_ - 1);
    int bt = idx >> 10;
    int t  = bt & (T_ - 1);
    int b  = bt >> 11;

    int token = tok[bt];
    float xc = emb[token * C_ + c];
    float xp;
    if (t == 0) {
        xp = xx_init[b * C_ + c];
    } else {
        xp = emb[tok[bt - 1] * C_ + c];
    }
    float mk = tmk[c], mv = tmv[c], mr = tmr[c];
    g_xk[idx] = xc * mk + xp * (1.0f - mk);
    g_xv[idx] = xc * mv + xp * (1.0f - mv);
    g_xr[idx] = xc * mr + xp * (1.0f - mr);
}

// ---------------------------------------------------------------------------
// K2: NT GEMM  C[M,N] = A[M,K] * W[N,K]^T   (M=16384, N=K=1024)
// blockIdx.z selects (xk,Wk)->k , (xv,Wv)->v , (xr,Wr)->sigmoid->r
// 128x128 tile, BK=8, 256 threads, 8x8 per thread.
// ---------------------------------------------------------------------------
#define BM 128
#define BN 128
#define BK 8

__global__ __launch_bounds__(256)
void gemm_nt_kernel(const float* __restrict__ Wk,
                    const float* __restrict__ Wv,
                    const float* __restrict__ Wr)
{
    const int which = blockIdx.z;
    const float* __restrict__ A = (which == 0) ? g_xk : (which == 1) ? g_xv : g_xr;
    const float* __restrict__ Bm = (which == 0) ? Wk  : (which == 1) ? Wv  : Wr;
    float* __restrict__ Cout     = (which == 0) ? g_k : (which == 1) ? g_v : g_r;

    const int K = C_;
    const int N = C_;

    __shared__ float As[BK][BM];
    __shared__ float Bs[BK][BN];

    const int tid  = threadIdx.x;
    const int ty   = tid >> 4;      // 0..15  -> M sub-tile
    const int tx   = tid & 15;      // 0..15  -> N sub-tile
    const int lrow = tid >> 1;      // 0..127 (load row)
    const int kofs = (tid & 1) * 4; // 0 or 4

    const int arow = blockIdx.y * BM + lrow;
    const int brow = blockIdx.x * BN + lrow;

    const float* Aptr = A  + (size_t)arow * K + kofs;
    const float* Bptr = Bm + (size_t)brow * K + kofs;

    float acc[8][8];
#pragma unroll
    for (int i = 0; i < 8; i++)
#pragma unroll
        for (int j = 0; j < 8; j++) acc[i][j] = 0.0f;

    for (int k0 = 0; k0 < K; k0 += BK) {
        float4 av = *(const float4*)(Aptr + k0);
        float4 bv = *(const float4*)(Bptr + k0);
        As[kofs + 0][lrow] = av.x;
        As[kofs + 1][lrow] = av.y;
        As[kofs + 2][lrow] = av.z;
        As[kofs + 3][lrow] = av.w;
        Bs[kofs + 0][lrow] = bv.x;
        Bs[kofs + 1][lrow] = bv.y;
        Bs[kofs + 2][lrow] = bv.z;
        Bs[kofs + 3][lrow] = bv.w;
        __syncthreads();

#pragma unroll
        for (int kk = 0; kk < BK; kk++) {
            float a[8], b[8];
            *(float4*)(a)     = *(const float4*)&As[kk][ty * 8];
            *(float4*)(a + 4) = *(const float4*)&As[kk][ty * 8 + 4];
            *(float4*)(b)     = *(const float4*)&Bs[kk][tx * 8];
            *(float4*)(b + 4) = *(const float4*)&Bs[kk][tx * 8 + 4];
#pragma unroll
            for (int i = 0; i < 8; i++)
#pragma unroll
                for (int j = 0; j < 8; j++)
                    acc[i][j] = fmaf(a[i], b[j], acc[i][j]);
        }
        __syncthreads();
    }

    const int crow0 = blockIdx.y * BM + ty * 8;
    const int ccol0 = blockIdx.x * BN + tx * 8;
#pragma unroll
    for (int i = 0; i < 8; i++) {
#pragma unroll
        for (int j = 0; j < 8; j += 4) {
            float4 o;
            o.x = acc[i][j + 0];
            o.y = acc[i][j + 1];
            o.z = acc[i][j + 2];
            o.w = acc[i][j + 3];
            if (which == 2) {
                o.x = 1.0f / (1.0f + __expf(-o.x));
                o.y = 1.0f / (1.0f + __expf(-o.y));
                o.z = 1.0f / (1.0f + __expf(-o.z));
                o.w = 1.0f / (1.0f + __expf(-o.w));
            }
            *(float4*)&Cout[(size_t)(crow0 + i) * N + ccol0 + j] = o;
        }
    }
}

// ---------------------------------------------------------------------------
// K3: WKV scan. One thread per (b,c) channel, sequential over T with
// 16-step register double-buffered prefetch to hide DRAM latency.
// Accumulates ysum (for mean) and ylast; writes z = 0.5*(ylast + ymean).
// ---------------------------------------------------------------------------
#define CH 16

__global__ __launch_bounds__(128)
void wkv_scan_kernel(const float* __restrict__ aa_init,
                     const float* __restrict__ bb_init,
                     const float* __restrict__ pp_init,
                     const float* __restrict__ time_decay,
                     const float* __restrict__ time_first)
{
    const int tidg = blockIdx.x * blockDim.x + threadIdx.x;  // 0..8191
    const int b = tidg >> 10;
    const int c = tidg & (C_ - 1);

    float aa = aa_init[tidg];
    float bb = bb_init[tidg];
    float pp = pp_init[tidg];
    const float w = -expf(time_decay[c]);
    const float u = time_first[c];

    float ysum = 0.0f;
    float ylast = 0.0f;

    const int base = b * T_ * C_ + c;

    float k0v[CH], v0v[CH], r0v[CH];
    float k1v[CH], v1v[CH], r1v[CH];

    // initial chunk load
    {
        int ba = base;
#pragma unroll
        for (int i = 0; i < CH; i++) {
            k0v[i] = g_k[ba + i * C_];
            v0v[i] = g_v[ba + i * C_];
            r0v[i] = g_r[ba + i * C_];
        }
    }

    const int nch = T_ / CH;  // 128
    for (int ch = 0; ch < nch; ch += 2) {
        // prefetch chunk ch+1 into buffer 1
        if (ch + 1 < nch) {
            int ba = base + (ch + 1) * CH * C_;
#pragma unroll
            for (int i = 0; i < CH; i++) {
                k1v[i] = g_k[ba + i * C_];
                v1v[i] = g_v[ba + i * C_];
                r1v[i] = g_r[ba + i * C_];
            }
        }
        // process buffer 0 (chunk ch)
#pragma unroll
        for (int i = 0; i < CH; i++) {
            float kt = k0v[i], vt = v0v[i], rt = r0v[i];
            float ww = u + kt;
            float p  = fmaxf(pp, ww);
            float e1 = __expf(pp - p);
            float e2 = __expf(ww - p);
            float num = e1 * aa + e2 * vt;
            float den = e1 * bb + e2;
            float y = rt * __fdividef(num, den);
            ysum += y;
            ylast = y;
            float ww2 = pp + w;
            float p2  = fmaxf(ww2, kt);
            float e1b = __expf(ww2 - p2);
            float e2b = __expf(kt - p2);
            aa = e1b * aa + e2b * vt;
            bb = e1b * bb + e2b;
            pp = p2;
        }
        // prefetch chunk ch+2 into buffer 0
        if (ch + 2 < nch) {
            int ba = base + (ch + 2) * CH * C_;
#pragma unroll
            for (int i = 0; i < CH; i++) {
                k0v[i] = g_k[ba + i * C_];
                v0v[i] = g_v[ba + i * C_];
                r0v[i] = g_r[ba + i * C_];
            }
        }
        // process buffer 1 (chunk ch+1)
#pragma unroll
        for (int i = 0; i < CH; i++) {
            float kt = k1v[i], vt = v1v[i], rt = r1v[i];
            float ww = u + kt;
            float p  = fmaxf(pp, ww);
            float e1 = __expf(pp - p);
            float e2 = __expf(ww - p);
            float num = e1 * aa + e2 * vt;
            float den = e1 * bb + e2;
            float y = rt * __fdividef(num, den);
            ysum += y;
            ylast = y;
            float ww2 = pp + w;
            float p2  = fmaxf(ww2, kt);
            float e1b = __expf(ww2 - p2);
            float e2b = __expf(kt - p2);
            aa = e1b * aa + e2b * vt;
            bb = e1b * bb + e2b;
            pp = p2;
        }
    }

    g_z[tidg] = 0.5f * (ylast + ysum * (1.0f / (float)T_));
}

// ---------------------------------------------------------------------------
// K4: tiny output GEMM: hx[b,d] = sum_c z[b,c] * Wo[d,c]; out = stack([hx,hx])
// One warp per (b,d) output.
// ---------------------------------------------------------------------------
__global__ __launch_bounds__(256)
void final_proj_kernel(const float* __restrict__ Wo,
                       float* __restrict__ out)
{
    int gw   = (blockIdx.x * blockDim.x + threadIdx.x) >> 5;  // warp id
    int lane = threadIdx.x & 31;
    if (gw >= B_ * C_) return;
    int b = gw >> 10;
    int d = gw & (C_ - 1);

    const float* z  = g_z + b * C_;
    const float* wr = Wo + (size_t)d * C_;
    float s = 0.0f;
#pragma unroll 8
    for (int c = lane; c < C_; c += 32)
        s = fmaf(z[c], wr[c], s);
#pragma unroll
    for (int o = 16; o > 0; o >>= 1)
        s += __shfl_xor_sync(0xFFFFFFFFu, s, o);
    if (lane == 0) {
        out[b * C_ + d]             = s;
        out[B_ * C_ + b * C_ + d]   = s;
    }
}

// ---------------------------------------------------------------------------
extern "C" void kernel_launch(void* const* d_in, const int* in_sizes, int n_in,
                              void* d_out, int out_size)
{
    const int*   tok  = (const int*)  d_in[0];
    const float* xx   = (const float*)d_in[1];
    const float* aa   = (const float*)d_in[2];
    const float* bb   = (const float*)d_in[3];
    const float* pp   = (const float*)d_in[4];
    const float* emb  = (const float*)d_in[5];
    const float* tmk  = (const float*)d_in[6];
    const float* tmv  = (const float*)d_in[7];
    const float* tmr  = (const float*)d_in[8];
    const float* tdec = (const float*)d_in[9];
    const float* tfir = (const float*)d_in[10];
    const float* Wk   = (const float*)d_in[11];
    const float* Wv   = (const float*)d_in[12];
    const float* Wr   = (const float*)d_in[13];
    const float* Wo   = (const float*)d_in[14];
    float* out = (float*)d_out;

    embed_mix_kernel<<<BTC / 256, 256>>>(tok, xx, emb, tmk, tmv, tmr);

    dim3 ggrid(C_ / BN, M_ / BM, 3);
    gemm_nt_kernel<<<ggrid, 256>>>(Wk, Wv, Wr);

    wkv_scan_kernel<<<(B_ * C_) / 128, 128>>>(aa, bb, pp, tdec, tfir);

    final_proj_kernel<<<(B_ * C_ * 32) / 256, 256>>>(Wo, out);
}

// round 3
// speedup vs baseline: 1.9414x; 1.9414x over previous
#include <cuda_runtime.h>
#include <cuda_bf16.h>
#include <cstdint>
#include <cmath>

// Problem constants
#define B_   8
#define T_   2048
#define C_   1024
#define M_   (B_*T_)       // 16384
#define BTC  (B_*T_*C_)    // 16777216

// ---------------------------------------------------------------------------
// Scratch (__device__ globals; no cudaMalloc allowed)
// ---------------------------------------------------------------------------
__device__ __nv_bfloat16 g_xk_hi[BTC], g_xk_lo[BTC];
__device__ __nv_bfloat16 g_xv_hi[BTC], g_xv_lo[BTC];
__device__ __nv_bfloat16 g_xr_hi[BTC], g_xr_lo[BTC];
__device__ __nv_bfloat16 g_W_hi[3][C_*C_];
__device__ __nv_bfloat16 g_W_lo[3][C_*C_];
__device__ float g_k[BTC], g_v[BTC], g_r[BTC];
__device__ float g_z[B_*C_];

// ---------------------------------------------------------------------------
// Generic-PTX helpers: cp.async, ldmatrix, mma.sync (all sm_80/75+; no
// arch-specific 'a' instructions — the harness compiles generic compute_103).
// ---------------------------------------------------------------------------
__device__ __forceinline__ uint32_t smem_u32(const void* p) {
    uint32_t a;
    asm("{ .reg .u64 t; cvta.to.shared.u64 t, %1; cvt.u32.u64 %0, t; }" : "=r"(a) : "l"(p));
    return a;
}
__device__ __forceinline__ void cpa16(uint32_t dst, const void* src) {
    asm volatile("cp.async.cg.shared.global [%0], [%1], 16;\n" :: "r"(dst), "l"(src));
}
__device__ __forceinline__ void cpa_commit() {
    asm volatile("cp.async.commit_group;\n" ::: "memory");
}
__device__ __forceinline__ void cpa_wait2() {
    asm volatile("cp.async.wait_group 2;\n" ::: "memory");
}
__device__ __forceinline__ void ldsm_x4(uint32_t& r0, uint32_t& r1, uint32_t& r2, uint32_t& r3,
                                        uint32_t addr) {
    asm volatile("ldmatrix.sync.aligned.m8n8.x4.shared.b16 {%0,%1,%2,%3}, [%4];"
                 : "=r"(r0), "=r"(r1), "=r"(r2), "=r"(r3) : "r"(addr));
}
__device__ __forceinline__ void ldsm_x2(uint32_t& r0, uint32_t& r1, uint32_t addr) {
    asm volatile("ldmatrix.sync.aligned.m8n8.x2.shared.b16 {%0,%1}, [%2];"
                 : "=r"(r0), "=r"(r1) : "r"(addr));
}
__device__ __forceinline__ void mma16816(float& d0, float& d1, float& d2, float& d3,
                                         uint32_t a0, uint32_t a1, uint32_t a2, uint32_t a3,
                                         uint32_t b0, uint32_t b1) {
    asm volatile(
        "mma.sync.aligned.m16n8k16.row.col.f32.bf16.bf16.f32 "
        "{%0,%1,%2,%3}, {%4,%5,%6,%7}, {%8,%9}, {%0,%1,%2,%3};"
        : "+f"(d0), "+f"(d1), "+f"(d2), "+f"(d3)
        : "r"(a0), "r"(a1), "r"(a2), "r"(a3), "r"(b0), "r"(b1));
}

// ---------------------------------------------------------------------------
// K0: weight split fp32 -> (hi, lo) bf16
// ---------------------------------------------------------------------------
__global__ __launch_bounds__(256)
void conv_w_kernel(const float* __restrict__ Wk,
                   const float* __restrict__ Wv,
                   const float* __restrict__ Wr)
{
    int which = blockIdx.y;
    int i = blockIdx.x * 256 + threadIdx.x;
    const float* src = (which == 0) ? Wk : (which == 1) ? Wv : Wr;
    float x = src[i];
    __nv_bfloat16 hi = __float2bfloat16_rn(x);
    __nv_bfloat16 lo = __float2bfloat16_rn(x - __bfloat162float(hi));
    g_W_hi[which][i] = hi;
    g_W_lo[which][i] = lo;
}

// ---------------------------------------------------------------------------
// K1: embedding gather + time-mix -> hi/lo bf16 xk, xv, xr
// ---------------------------------------------------------------------------
__global__ __launch_bounds__(256)
void embed_mix_kernel(const int*   __restrict__ tok,
                      const float* __restrict__ xx_init,
                      const float* __restrict__ emb,
                      const float* __restrict__ tmk,
                      const float* __restrict__ tmv,
                      const float* __restrict__ tmr)
{
    int idx = blockIdx.x * blockDim.x + threadIdx.x;   // < BTC
    int c  = idx & (C_ - 1);
    int bt = idx >> 10;
    int t  = bt & (T_ - 1);
    int b  = bt >> 11;

    int token = tok[bt];
    float xc = emb[token * C_ + c];
    float xp;
    if (t == 0) xp = xx_init[b * C_ + c];
    else        xp = emb[tok[bt - 1] * C_ + c];

    float mk = tmk[c], mv = tmv[c], mr = tmr[c];
    float xk = xc * mk + xp * (1.0f - mk);
    float xv = xc * mv + xp * (1.0f - mv);
    float xr = xc * mr + xp * (1.0f - mr);

    __nv_bfloat16 h;
    h = __float2bfloat16_rn(xk); g_xk_hi[idx] = h;
    g_xk_lo[idx] = __float2bfloat16_rn(xk - __bfloat162float(h));
    h = __float2bfloat16_rn(xv); g_xv_hi[idx] = h;
    g_xv_lo[idx] = __float2bfloat16_rn(xv - __bfloat162float(h));
    h = __float2bfloat16_rn(xr); g_xr_hi[idx] = h;
    g_xr_lo[idx] = __float2bfloat16_rn(xr - __bfloat162float(h));
}

// ---------------------------------------------------------------------------
// K2: hi/lo-split bf16 NT GEMM via mma.sync.m16n8k16.
// C[M,N] = A[M,K]*W[N,K]^T,  A*W ~= Ahi*Whi + Ahi*Wlo + Alo*Whi
// fused as one virtual K = 3*1024 accumulation.
// Tiles: 128x128x32, 8 warps (warp tile 64x32), 3-stage cp.async pipeline.
// SMEM rows padded to 80B (BK*2 = 64B data) => conflict-free ldmatrix.
// blockIdx.z: 0 -> k, 1 -> v, 2 -> sigmoid -> r
// ---------------------------------------------------------------------------
#define BM 128
#define BN 128
#define BK 32
#define ROWB 80                      // padded row bytes (64 data + 16 pad)
#define STAGE_A (BM * ROWB)          // 10240
#define STAGE_B (BN * ROWB)          // 10240
#define STAGEB  (STAGE_A + STAGE_B)  // 20480
#define NSTAGE 3
#define GEMM_SMEM (NSTAGE * STAGEB)  // 61440
#define NKV (3 * C_ / BK)            // 96 virtual K-chunks

__global__ __launch_bounds__(256)
void gemm_mma_kernel()
{
    extern __shared__ char smem[];
    const uint32_t sb = smem_u32(smem);
    const int tid  = threadIdx.x;
    const int wid  = tid >> 5;
    const int lane = tid & 31;

    const int which = blockIdx.z;
    const int n0 = blockIdx.x * BN;
    const int m0 = blockIdx.y * BM;

    const __nv_bfloat16* Ahi = (which == 0) ? g_xk_hi : (which == 1) ? g_xv_hi : g_xr_hi;
    const __nv_bfloat16* Alo = (which == 0) ? g_xk_lo : (which == 1) ? g_xv_lo : g_xr_lo;
    const __nv_bfloat16* Whi = g_W_hi[which];
    const __nv_bfloat16* Wlo = g_W_lo[which];
    float* __restrict__ Cout = (which == 0) ? g_k : (which == 1) ? g_v : g_r;

    // phase -> operand pointers (virtual K extension)
    const __nv_bfloat16* Aph[3] = { Ahi, Ahi, Alo };
    const __nv_bfloat16* Wph[3] = { Whi, Wlo, Whi };

    const int warp_m = (wid & 1) * 64;   // 2 warps along M
    const int warp_n = (wid >> 1) * 32;  // 4 warps along N

    float acc[4][4][4];
#pragma unroll
    for (int i = 0; i < 4; i++)
#pragma unroll
        for (int j = 0; j < 4; j++)
#pragma unroll
            for (int q = 0; q < 4; q++) acc[i][j][q] = 0.0f;

    // ---- async tile loader: 512 A-chunks + 512 B-chunks of 16B, 4 per thread
    auto issue_stage = [&](int kt, int stg) {
        const int phase = kt >> 5;
        const int k0b = (kt & 31) * BK * 2;     // byte offset along K
        const char* Ag = (const char*)Aph[phase] + (size_t)m0 * (C_ * 2) + k0b;
        const char* Wg = (const char*)Wph[phase] + (size_t)n0 * (C_ * 2) + k0b;
        uint32_t abase = sb + stg * STAGEB;
        uint32_t bbase = abase + STAGE_A;
#pragma unroll
        for (int rep = 0; rep < 2; rep++) {
            int g = tid + rep * 256;            // 0..511
            int row = g >> 2;
            int ck  = g & 3;
            cpa16(abase + row * ROWB + ck * 16, Ag + (size_t)row * (C_ * 2) + ck * 16);
            cpa16(bbase + row * ROWB + ck * 16, Wg + (size_t)row * (C_ * 2) + ck * 16);
        }
        cpa_commit();
    };

    issue_stage(0, 0);
    issue_stage(1, 1);

    const int l15 = lane & 15;
    const int l7  = lane & 7;

    for (int kt = 0; kt < NKV; kt++) {
        if (kt + 2 < NKV) issue_stage(kt + 2, (kt + 2) % NSTAGE);
        else              cpa_commit();         // keep group accounting uniform
        cpa_wait2();
        __syncthreads();

        const uint32_t abase = sb + (kt % NSTAGE) * STAGEB;
        const uint32_t bbase = abase + STAGE_A;

#pragma unroll
        for (int ks = 0; ks < 2; ks++) {
            uint32_t a[4][4];
            uint32_t b[4][2];
            // A fragments: addr = (warp_m + mt*16 + lane&15)*80 + ks*32 + (lane>>4)*16
            uint32_t aoff = abase + (warp_m + l15) * ROWB + ks * 32 + (lane >> 4) * 16;
#pragma unroll
            for (int mt = 0; mt < 4; mt++)
                ldsm_x4(a[mt][0], a[mt][1], a[mt][2], a[mt][3], aoff + mt * (16 * ROWB));
            // B fragments: lanes 0-7 rows n..n+7 @k0, lanes 8-15 same rows @+16B
            uint32_t boff = bbase + (warp_n + l7) * ROWB + ks * 32 + ((lane >> 3) & 1) * 16;
#pragma unroll
            for (int nt = 0; nt < 4; nt++)
                ldsm_x2(b[nt][0], b[nt][1], boff + nt * (8 * ROWB));
#pragma unroll
            for (int mt = 0; mt < 4; mt++)
#pragma unroll
                for (int nt = 0; nt < 4; nt++)
                    mma16816(acc[mt][nt][0], acc[mt][nt][1], acc[mt][nt][2], acc[mt][nt][3],
                             a[mt][0], a[mt][1], a[mt][2], a[mt][3],
                             b[nt][0], b[nt][1]);
        }
        __syncthreads();
    }

    // ---- epilogue: direct register -> global stores (float2 per fragment half)
    const int rbase = m0 + warp_m + (lane >> 2);
    const int cbase = n0 + warp_n + (lane & 3) * 2;
#pragma unroll
    for (int mt = 0; mt < 4; mt++) {
#pragma unroll
        for (int nt = 0; nt < 4; nt++) {
            float v0 = acc[mt][nt][0], v1 = acc[mt][nt][1];
            float v2 = acc[mt][nt][2], v3 = acc[mt][nt][3];
            if (which == 2) {
                v0 = 1.0f / (1.0f + __expf(-v0));
                v1 = 1.0f / (1.0f + __expf(-v1));
                v2 = 1.0f / (1.0f + __expf(-v2));
                v3 = 1.0f / (1.0f + __expf(-v3));
            }
            size_t r0 = (size_t)(rbase + mt * 16) * C_ + cbase + nt * 8;
            size_t r1 = r0 + 8 * C_;
            *(float2*)&Cout[r0] = make_float2(v0, v1);
            *(float2*)&Cout[r1] = make_float2(v2, v3);
        }
    }
}

// ---------------------------------------------------------------------------
// K3: WKV scan (latency-chain bound, register double-buffered prefetch)
// ---------------------------------------------------------------------------
#define CH 16

__global__ __launch_bounds__(128)
void wkv_scan_kernel(const float* __restrict__ aa_init,
                     const float* __restrict__ bb_init,
                     const float* __restrict__ pp_init,
                     const float* __restrict__ time_decay,
                     const float* __restrict__ time_first)
{
    const int tidg = blockIdx.x * blockDim.x + threadIdx.x;  // 0..8191
    const int b = tidg >> 10;
    const int c = tidg & (C_ - 1);

    float aa = aa_init[tidg];
    float bb = bb_init[tidg];
    float pp = pp_init[tidg];
    const float w = -expf(time_decay[c]);
    const float u = time_first[c];

    float ysum = 0.0f;
    float ylast = 0.0f;

    const int base = b * T_ * C_ + c;

    float k0v[CH], v0v[CH], r0v[CH];
    float k1v[CH], v1v[CH], r1v[CH];

    {
        int ba = base;
#pragma unroll
        for (int i = 0; i < CH; i++) {
            k0v[i] = g_k[ba + i * C_];
            v0v[i] = g_v[ba + i * C_];
            r0v[i] = g_r[ba + i * C_];
        }
    }

    const int nch = T_ / CH;  // 128
    for (int ch = 0; ch < nch; ch += 2) {
        if (ch + 1 < nch) {
            int ba = base + (ch + 1) * CH * C_;
#pragma unroll
            for (int i = 0; i < CH; i++) {
                k1v[i] = g_k[ba + i * C_];
                v1v[i] = g_v[ba + i * C_];
                r1v[i] = g_r[ba + i * C_];
            }
        }
#pragma unroll
        for (int i = 0; i < CH; i++) {
            float kt = k0v[i], vt = v0v[i], rt = r0v[i];
            float ww = u + kt;
            float p  = fmaxf(pp, ww);
            float e1 = __expf(pp - p);
            float e2 = __expf(ww - p);
            float y = rt * __fdividef(e1 * aa + e2 * vt, e1 * bb + e2);
            ysum += y;
            ylast = y;
            float ww2 = pp + w;
            float p2  = fmaxf(ww2, kt);
            float e1b = __expf(ww2 - p2);
            float e2b = __expf(kt - p2);
            aa = e1b * aa + e2b * vt;
            bb = e1b * bb + e2b;
            pp = p2;
        }
        if (ch + 2 < nch) {
            int ba = base + (ch + 2) * CH * C_;
#pragma unroll
            for (int i = 0; i < CH; i++) {
                k0v[i] = g_k[ba + i * C_];
                v0v[i] = g_v[ba + i * C_];
                r0v[i] = g_r[ba + i * C_];
            }
        }
#pragma unroll
        for (int i = 0; i < CH; i++) {
            float kt = k1v[i], vt = v1v[i], rt = r1v[i];
            float ww = u + kt;
            float p  = fmaxf(pp, ww);
            float e1 = __expf(pp - p);
            float e2 = __expf(ww - p);
            float y = rt * __fdividef(e1 * aa + e2 * vt, e1 * bb + e2);
            ysum += y;
            ylast = y;
            float ww2 = pp + w;
            float p2  = fmaxf(ww2, kt);
            float e1b = __expf(ww2 - p2);
            float e2b = __expf(kt - p2);
            aa = e1b * aa + e2b * vt;
            bb = e1b * bb + e2b;
            pp = p2;
        }
    }

    g_z[tidg] = 0.5f * (ylast + ysum * (1.0f / (float)T_));
}

// ---------------------------------------------------------------------------
// K4: tiny output GEMM hx[b,d] = sum_c z[b,c] * Wo[d,c]; out = stack([hx,hx])
// ---------------------------------------------------------------------------
__global__ __launch_bounds__(256)
void final_proj_kernel(const float* __restrict__ Wo,
                       float* __restrict__ out)
{
    int gw   = (blockIdx.x * blockDim.x + threadIdx.x) >> 5;
    int lane = threadIdx.x & 31;
    if (gw >= B_ * C_) return;
    int b = gw >> 10;
    int d = gw & (C_ - 1);

    const float* z  = g_z + b * C_;
    const float* wr = Wo + (size_t)d * C_;
    float s = 0.0f;
#pragma unroll 8
    for (int c = lane; c < C_; c += 32)
        s = fmaf(z[c], wr[c], s);
#pragma unroll
    for (int o = 16; o > 0; o >>= 1)
        s += __shfl_xor_sync(0xFFFFFFFFu, s, o);
    if (lane == 0) {
        out[b * C_ + d]           = s;
        out[B_ * C_ + b * C_ + d] = s;
    }
}

// ---------------------------------------------------------------------------
extern "C" void kernel_launch(void* const* d_in, const int* in_sizes, int n_in,
                              void* d_out, int out_size)
{
    const int*   tok  = (const int*)  d_in[0];
    const float* xx   = (const float*)d_in[1];
    const float* aa   = (const float*)d_in[2];
    const float* bb   = (const float*)d_in[3];
    const float* pp   = (const float*)d_in[4];
    const float* emb  = (const float*)d_in[5];
    const float* tmk  = (const float*)d_in[6];
    const float* tmv  = (const float*)d_in[7];
    const float* tmr  = (const float*)d_in[8];
    const float* tdec = (const float*)d_in[9];
    const float* tfir = (const float*)d_in[10];
    const float* Wk   = (const float*)d_in[11];
    const float* Wv   = (const float*)d_in[12];
    const float* Wr   = (const float*)d_in[13];
    const float* Wo   = (const float*)d_in[14];
    float* out = (float*)d_out;

    cudaFuncSetAttribute(gemm_mma_kernel,
                         cudaFuncAttributeMaxDynamicSharedMemorySize, GEMM_SMEM);

    dim3 wgrid(C_ * C_ / 256, 3);
    conv_w_kernel<<<wgrid, 256>>>(Wk, Wv, Wr);

    embed_mix_kernel<<<BTC / 256, 256>>>(tok, xx, emb, tmk, tmv, tmr);

    dim3 ggrid(C_ / BN, M_ / BM, 3);   // (8, 128, 3); x-fastest => A reuse in L2
    gemm_mma_kernel<<<ggrid, 256, GEMM_SMEM>>>();

    wkv_scan_kernel<<<(B_ * C_) / 128, 128>>>(aa, bb, pp, tdec, tfir);

    final_proj_kernel<<<(B_ * C_ * 32) / 256, 256>>>(Wo, out);
}

// round 4
// speedup vs baseline: 2.3561x; 1.2136x over previous
#include <cuda_runtime.h>
#include <cuda_bf16.h>
#include <cstdint>
#include <cmath>

// Problem constants
#define B_   8
#define T_   2048
#define C_   1024
#define M_   (B_*T_)       // 16384
#define BTC  (B_*T_*C_)    // 16777216

// ---------------------------------------------------------------------------
// Scratch (__device__ globals; no cudaMalloc allowed)
// ---------------------------------------------------------------------------
__device__ __nv_bfloat16 g_xk_hi[BTC], g_xk_lo[BTC];
__device__ __nv_bfloat16 g_xv_hi[BTC], g_xv_lo[BTC];
__device__ __nv_bfloat16 g_xr_hi[BTC], g_xr_lo[BTC];
__device__ __nv_bfloat16 g_W_hi[3][C_*C_];
__device__ __nv_bfloat16 g_W_lo[3][C_*C_];
__device__ float g_k[BTC], g_v[BTC], g_r[BTC];
__device__ float g_z[B_*C_];

// ---------------------------------------------------------------------------
// Generic-PTX helpers (sm_80-class; safe for the harness's compute_103 build)
// ---------------------------------------------------------------------------
__device__ __forceinline__ uint32_t smem_u32(const void* p) {
    uint32_t a;
    asm("{ .reg .u64 t; cvta.to.shared.u64 t, %1; cvt.u32.u64 %0, t; }" : "=r"(a) : "l"(p));
    return a;
}
__device__ __forceinline__ void cpa16(uint32_t dst, const void* src) {
    asm volatile("cp.async.cg.shared.global [%0], [%1], 16;\n" :: "r"(dst), "l"(src));
}
__device__ __forceinline__ void cpa_commit() {
    asm volatile("cp.async.commit_group;\n" ::: "memory");
}
__device__ __forceinline__ void cpa_wait1() {
    asm volatile("cp.async.wait_group 1;\n" ::: "memory");
}
__device__ __forceinline__ void cpa_wait0() {
    asm volatile("cp.async.wait_group 0;\n" ::: "memory");
}
__device__ __forceinline__ void ldsm_x4(uint32_t& r0, uint32_t& r1, uint32_t& r2, uint32_t& r3,
                                        uint32_t addr) {
    asm volatile("ldmatrix.sync.aligned.m8n8.x4.shared.b16 {%0,%1,%2,%3}, [%4];"
                 : "=r"(r0), "=r"(r1), "=r"(r2), "=r"(r3) : "r"(addr));
}
__device__ __forceinline__ void ldsm_x2(uint32_t& r0, uint32_t& r1, uint32_t addr) {
    asm volatile("ldmatrix.sync.aligned.m8n8.x2.shared.b16 {%0,%1}, [%2];"
                 : "=r"(r0), "=r"(r1) : "r"(addr));
}
__device__ __forceinline__ void mma16816(float& d0, float& d1, float& d2, float& d3,
                                         uint32_t a0, uint32_t a1, uint32_t a2, uint32_t a3,
                                         uint32_t b0, uint32_t b1) {
    asm volatile(
        "mma.sync.aligned.m16n8k16.row.col.f32.bf16.bf16.f32 "
        "{%0,%1,%2,%3}, {%4,%5,%6,%7}, {%8,%9}, {%0,%1,%2,%3};"
        : "+f"(d0), "+f"(d1), "+f"(d2), "+f"(d3)
        : "r"(a0), "r"(a1), "r"(a2), "r"(a3), "r"(b0), "r"(b1));
}

// ---------------------------------------------------------------------------
// K0: weight split fp32 -> (hi, lo) bf16
// ---------------------------------------------------------------------------
__global__ __launch_bounds__(256)
void conv_w_kernel(const float* __restrict__ Wk,
                   const float* __restrict__ Wv,
                   const float* __restrict__ Wr)
{
    int which = blockIdx.y;
    int i = blockIdx.x * 256 + threadIdx.x;
    const float* src = (which == 0) ? Wk : (which == 1) ? Wv : Wr;
    float x = src[i];
    __nv_bfloat16 hi = __float2bfloat16_rn(x);
    __nv_bfloat16 lo = __float2bfloat16_rn(x - __bfloat162float(hi));
    g_W_hi[which][i] = hi;
    g_W_lo[which][i] = lo;
}

// ---------------------------------------------------------------------------
// K1: embedding gather + time-mix -> hi/lo bf16 xk, xv, xr
// ---------------------------------------------------------------------------
__global__ __launch_bounds__(256)
void embed_mix_kernel(const int*   __restrict__ tok,
                      const float* __restrict__ xx_init,
                      const float* __restrict__ emb,
                      const float* __restrict__ tmk,
                      const float* __restrict__ tmv,
                      const float* __restrict__ tmr)
{
    int idx = blockIdx.x * blockDim.x + threadIdx.x;   // < BTC
    int c  = idx & (C_ - 1);
    int bt = idx >> 10;
    int t  = bt & (T_ - 1);
    int b  = bt >> 11;

    int token = tok[bt];
    float xc = emb[token * C_ + c];
    float xp;
    if (t == 0) xp = xx_init[b * C_ + c];
    else        xp = emb[tok[bt - 1] * C_ + c];

    float mk = tmk[c], mv = tmv[c], mr = tmr[c];
    float xk = xc * mk + xp * (1.0f - mk);
    float xv = xc * mv + xp * (1.0f - mv);
    float xr = xc * mr + xp * (1.0f - mr);

    __nv_bfloat16 h;
    h = __float2bfloat16_rn(xk); g_xk_hi[idx] = h;
    g_xk_lo[idx] = __float2bfloat16_rn(xk - __bfloat162float(h));
    h = __float2bfloat16_rn(xv); g_xv_hi[idx] = h;
    g_xv_lo[idx] = __float2bfloat16_rn(xv - __bfloat162float(h));
    h = __float2bfloat16_rn(xr); g_xr_hi[idx] = h;
    g_xr_lo[idx] = __float2bfloat16_rn(xr - __bfloat162float(h));
}

// ---------------------------------------------------------------------------
// K2: hi/lo-split bf16 NT GEMM, shared-operand 3-term form:
//   C = Ahi*Whi + Alo*Whi + Ahi*Wlo  (all terms reuse the same smem tiles)
// Tiles: 128x256x32 physical-K, 8 warps (warp tile 64x64), 2-stage cp.async.
// SMEM rows padded to 80B => conflict-free ldmatrix.
// blockIdx.z: 0 -> k, 1 -> v, 2 -> sigmoid -> r
// ---------------------------------------------------------------------------
#define BM 128
#define BN 256
#define BK 32
#define ROWB 80
#define AT_BYTES (BM * ROWB)             // 10240 per A tile
#define BT_BYTES (BN * ROWB)             // 20480 per B tile
#define STAGEB (2*AT_BYTES + 2*BT_BYTES) // 61440
#define GEMM_SMEM (2 * STAGEB)           // 122880
#define NKT (C_ / BK)                    // 32 physical K-chunks

__global__ __launch_bounds__(256, 1)
void gemm_mma_kernel()
{
    extern __shared__ char smem[];
    const uint32_t sb = smem_u32(smem);
    const int tid  = threadIdx.x;
    const int wid  = tid >> 5;
    const int lane = tid & 31;

    const int which = blockIdx.z;
    const int n0 = blockIdx.x * BN;
    const int m0 = blockIdx.y * BM;

    const __nv_bfloat16* Ahi = (which == 0) ? g_xk_hi : (which == 1) ? g_xv_hi : g_xr_hi;
    const __nv_bfloat16* Alo = (which == 0) ? g_xk_lo : (which == 1) ? g_xv_lo : g_xr_lo;
    const __nv_bfloat16* Whi = g_W_hi[which];
    const __nv_bfloat16* Wlo = g_W_lo[which];
    float* __restrict__ Cout = (which == 0) ? g_k : (which == 1) ? g_v : g_r;

    const char* Ahi_g = (const char*)(Ahi + (size_t)m0 * C_);
    const char* Alo_g = (const char*)(Alo + (size_t)m0 * C_);
    const char* Whi_g = (const char*)(Whi + (size_t)n0 * C_);
    const char* Wlo_g = (const char*)(Wlo + (size_t)n0 * C_);

    const int warp_m = (wid & 1) * 64;   // 2 warps along M
    const int warp_n = (wid >> 1) * 64;  // 4 warps along N

    float acc[4][8][4];
#pragma unroll
    for (int i = 0; i < 4; i++)
#pragma unroll
        for (int j = 0; j < 8; j++)
#pragma unroll
            for (int q = 0; q < 4; q++) acc[i][j][q] = 0.0f;

    // Load one physical K-chunk: Ahi, Alo (128x64B), Whi, Wlo (256x64B)
    auto issue_stage = [&](int kt, int stg) {
        const int kb = kt * BK * 2;              // byte offset along K
        uint32_t base = sb + stg * STAGEB;
        // A granules: 2 tiles x 128 rows x 4 x16B = 1024
        for (int g = tid; g < 1024; g += 256) {
            int t = g >> 9;
            int r = (g >> 2) & 127;
            int c = g & 3;
            const char* src = (t ? Alo_g : Ahi_g) + (size_t)r * (C_ * 2) + kb + c * 16;
            cpa16(base + t * AT_BYTES + r * ROWB + c * 16, src);
        }
        // B granules: 2 tiles x 256 rows x 4 x16B = 2048
        for (int g = tid; g < 2048; g += 256) {
            int t = g >> 10;
            int r = (g >> 2) & 255;
            int c = g & 3;
            const char* src = (t ? Wlo_g : Whi_g) + (size_t)r * (C_ * 2) + kb + c * 16;
            cpa16(base + 2 * AT_BYTES + t * BT_BYTES + r * ROWB + c * 16, src);
        }
        cpa_commit();
    };

    issue_stage(0, 0);
    issue_stage(1, 1);

    const int l15 = lane & 15;
    const int l7  = lane & 7;

    for (int kt = 0; kt < NKT; kt++) {
        if (kt == NKT - 1) cpa_wait0(); else cpa_wait1();
        __syncthreads();

        const uint32_t base = sb + (kt & 1) * STAGEB;
        const uint32_t ah = base;
        const uint32_t al = base + AT_BYTES;
        const uint32_t bh = base + 2 * AT_BYTES;
        const uint32_t bl = base + 2 * AT_BYTES + BT_BYTES;

#pragma unroll
        for (int ks = 0; ks < 2; ks++) {
            uint32_t ahi_f[4][4], alo_f[4][4];
            uint32_t bf[8][2];
            const uint32_t arow = (warp_m + l15) * ROWB + ks * 32 + (lane >> 4) * 16;
#pragma unroll
            for (int mt = 0; mt < 4; mt++) {
                ldsm_x4(ahi_f[mt][0], ahi_f[mt][1], ahi_f[mt][2], ahi_f[mt][3],
                        ah + arow + mt * (16 * ROWB));
                ldsm_x4(alo_f[mt][0], alo_f[mt][1], alo_f[mt][2], alo_f[mt][3],
                        al + arow + mt * (16 * ROWB));
            }
            const uint32_t brow = (warp_n + l7) * ROWB + ks * 32 + ((lane >> 3) & 1) * 16;
            // B hi: terms hi*hi and lo*hi
#pragma unroll
            for (int nt = 0; nt < 8; nt++)
                ldsm_x2(bf[nt][0], bf[nt][1], bh + brow + nt * (8 * ROWB));
#pragma unroll
            for (int mt = 0; mt < 4; mt++)
#pragma unroll
                for (int nt = 0; nt < 8; nt++)
                    mma16816(acc[mt][nt][0], acc[mt][nt][1], acc[mt][nt][2], acc[mt][nt][3],
                             ahi_f[mt][0], ahi_f[mt][1], ahi_f[mt][2], ahi_f[mt][3],
                             bf[nt][0], bf[nt][1]);
#pragma unroll
            for (int mt = 0; mt < 4; mt++)
#pragma unroll
                for (int nt = 0; nt < 8; nt++)
                    mma16816(acc[mt][nt][0], acc[mt][nt][1], acc[mt][nt][2], acc[mt][nt][3],
                             alo_f[mt][0], alo_f[mt][1], alo_f[mt][2], alo_f[mt][3],
                             bf[nt][0], bf[nt][1]);
            // B lo: term hi*lo (reuse bf registers)
#pragma unroll
            for (int nt = 0; nt < 8; nt++)
                ldsm_x2(bf[nt][0], bf[nt][1], bl + brow + nt * (8 * ROWB));
#pragma unroll
            for (int mt = 0; mt < 4; mt++)
#pragma unroll
                for (int nt = 0; nt < 8; nt++)
                    mma16816(acc[mt][nt][0], acc[mt][nt][1], acc[mt][nt][2], acc[mt][nt][3],
                             ahi_f[mt][0], ahi_f[mt][1], ahi_f[mt][2], ahi_f[mt][3],
                             bf[nt][0], bf[nt][1]);
        }
        __syncthreads();
        if (kt + 2 < NKT) issue_stage(kt + 2, kt & 1);
    }

    // ---- epilogue: direct register -> global stores
    const int rbase = m0 + warp_m + (lane >> 2);
    const int cbase = n0 + warp_n + (lane & 3) * 2;
#pragma unroll
    for (int mt = 0; mt < 4; mt++) {
#pragma unroll
        for (int nt = 0; nt < 8; nt++) {
            float v0 = acc[mt][nt][0], v1 = acc[mt][nt][1];
            float v2 = acc[mt][nt][2], v3 = acc[mt][nt][3];
            if (which == 2) {
                v0 = 1.0f / (1.0f + __expf(-v0));
                v1 = 1.0f / (1.0f + __expf(-v1));
                v2 = 1.0f / (1.0f + __expf(-v2));
                v3 = 1.0f / (1.0f + __expf(-v3));
            }
            size_t r0 = (size_t)(rbase + mt * 16) * C_ + cbase + nt * 8;
            size_t r1 = r0 + 8 * C_;
            *(float2*)&Cout[r0] = make_float2(v0, v1);
            *(float2*)&Cout[r1] = make_float2(v2, v3);
        }
    }
}

// ---------------------------------------------------------------------------
// K3: WKV scan. 128 blocks x 64 threads = one wave over 128 SMs.
// MUFU-reduced step: exp(min-max) only (the other factor is exactly 1).
// ---------------------------------------------------------------------------
#define CH 16

__global__ __launch_bounds__(64)
void wkv_scan_kernel(const float* __restrict__ aa_init,
                     const float* __restrict__ bb_init,
                     const float* __restrict__ pp_init,
                     const float* __restrict__ time_decay,
                     const float* __restrict__ time_first)
{
    const int tidg = blockIdx.x * blockDim.x + threadIdx.x;  // 0..8191
    const int b = tidg >> 10;
    const int c = tidg & (C_ - 1);

    float aa = aa_init[tidg];
    float bb = bb_init[tidg];
    float pp = pp_init[tidg];
    const float w = -expf(time_decay[c]);
    const float u = time_first[c];

    float ysum = 0.0f;
    float ylast = 0.0f;

    const int base = b * T_ * C_ + c;

    float k0v[CH], v0v[CH], r0v[CH];
    float k1v[CH], v1v[CH], r1v[CH];

    {
        int ba = base;
#pragma unroll
        for (int i = 0; i < CH; i++) {
            k0v[i] = g_k[ba + i * C_];
            v0v[i] = g_v[ba + i * C_];
            r0v[i] = g_r[ba + i * C_];
        }
    }

#define WKV_STEP(kt, vt, rt) do {                                   \
        float ww = u + (kt);                                        \
        float d  = pp - ww;                                         \
        float es = __expf(-fabsf(d));                               \
        float e1 = (d >= 0.0f) ? 1.0f : es;                         \
        float e2 = (d >= 0.0f) ? es : 1.0f;                         \
        float y = (rt) * __fdividef(e1 * aa + e2 * (vt), e1 * bb + e2); \
        ysum += y;                                                  \
        ylast = y;                                                  \
        float ww2 = pp + w;                                         \
        float d2  = ww2 - (kt);                                     \
        float es2 = __expf(-fabsf(d2));                             \
        float e1b = (d2 >= 0.0f) ? 1.0f : es2;                      \
        float e2b = (d2 >= 0.0f) ? es2 : 1.0f;                      \
        aa = e1b * aa + e2b * (vt);                                 \
        bb = e1b * bb + e2b;                                        \
        pp = fmaxf(ww2, (kt));                                      \
    } while (0)

    const int nch = T_ / CH;  // 128
    for (int ch = 0; ch < nch; ch += 2) {
        if (ch + 1 < nch) {
            int ba = base + (ch + 1) * CH * C_;
#pragma unroll
            for (int i = 0; i < CH; i++) {
                k1v[i] = g_k[ba + i * C_];
                v1v[i] = g_v[ba + i * C_];
                r1v[i] = g_r[ba + i * C_];
            }
        }
#pragma unroll
        for (int i = 0; i < CH; i++) WKV_STEP(k0v[i], v0v[i], r0v[i]);
        if (ch + 2 < nch) {
            int ba = base + (ch + 2) * CH * C_;
#pragma unroll
            for (int i = 0; i < CH; i++) {
                k0v[i] = g_k[ba + i * C_];
                v0v[i] = g_v[ba + i * C_];
                r0v[i] = g_r[ba + i * C_];
            }
        }
#pragma unroll
        for (int i = 0; i < CH; i++) WKV_STEP(k1v[i], v1v[i], r1v[i]);
    }

    g_z[tidg] = 0.5f * (ylast + ysum * (1.0f / (float)T_));
}

// ---------------------------------------------------------------------------
// K4: tiny output GEMM hx[b,d] = sum_c z[b,c] * Wo[d,c]; out = stack([hx,hx])
// ---------------------------------------------------------------------------
__global__ __launch_bounds__(256)
void final_proj_kernel(const float* __restrict__ Wo,
                       float* __restrict__ out)
{
    int gw   = (blockIdx.x * blockDim.x + threadIdx.x) >> 5;
    int lane = threadIdx.x & 31;
    if (gw >= B_ * C_) return;
    int b = gw >> 10;
    int d = gw & (C_ - 1);

    const float* z  = g_z + b * C_;
    const float* wr = Wo + (size_t)d * C_;
    float s = 0.0f;
#pragma unroll 8
    for (int c = lane; c < C_; c += 32)
        s = fmaf(z[c], wr[c], s);
#pragma unroll
    for (int o = 16; o > 0; o >>= 1)
        s += __shfl_xor_sync(0xFFFFFFFFu, s, o);
    if (lane == 0) {
        out[b * C_ + d]           = s;
        out[B_ * C_ + b * C_ + d] = s;
    }
}

// ---------------------------------------------------------------------------
extern "C" void kernel_launch(void* const* d_in, const int* in_sizes, int n_in,
                              void* d_out, int out_size)
{
    const int*   tok  = (const int*)  d_in[0];
    const float* xx   = (const float*)d_in[1];
    const float* aa   = (const float*)d_in[2];
    const float* bb   = (const float*)d_in[3];
    const float* pp   = (const float*)d_in[4];
    const float* emb  = (const float*)d_in[5];
    const float* tmk  = (const float*)d_in[6];
    const float* tmv  = (const float*)d_in[7];
    const float* tmr  = (const float*)d_in[8];
    const float* tdec = (const float*)d_in[9];
    const float* tfir = (const float*)d_in[10];
    const float* Wk   = (const float*)d_in[11];
    const float* Wv   = (const float*)d_in[12];
    const float* Wr   = (const float*)d_in[13];
    const float* Wo   = (const float*)d_in[14];
    float* out = (float*)d_out;

    cudaFuncSetAttribute(gemm_mma_kernel,
                         cudaFuncAttributeMaxDynamicSharedMemorySize, GEMM_SMEM);

    dim3 wgrid(C_ * C_ / 256, 3);
    conv_w_kernel<<<wgrid, 256>>>(Wk, Wv, Wr);

    embed_mix_kernel<<<BTC / 256, 256>>>(tok, xx, emb, tmk, tmv, tmr);

    dim3 ggrid(C_ / BN, M_ / BM, 3);   // (4, 128, 3)
    gemm_mma_kernel<<<ggrid, 256, GEMM_SMEM>>>();

    wkv_scan_kernel<<<(B_ * C_) / 64, 64>>>(aa, bb, pp, tdec, tfir);

    final_proj_kernel<<<(B_ * C_ * 32) / 256, 256>>>(Wo, out);
}

// round 5
// speedup vs baseline: 3.4405x; 1.4603x over previous
#include <cuda_runtime.h>
#include <cuda_fp16.h>
#include <cstdint>
#include <cmath>

// Problem constants
#define B_   8
#define T_   2048
#define C_   1024
#define M_   (B_*T_)       // 16384
#define BTC  (B_*T_*C_)    // 16777216
#define BC_  (B_*C_)       // 8192

// Chunked scan
#define NCH 16
#define CL  (T_/NCH)       // 128

// ---------------------------------------------------------------------------
// Scratch (__device__ globals; no cudaMalloc allowed)
// ---------------------------------------------------------------------------
__device__ __half g_xk_hi[BTC], g_xk_lo[BTC];
__device__ __half g_xv_hi[BTC], g_xv_lo[BTC];
__device__ __half g_xr_hi[BTC], g_xr_lo[BTC];
__device__ __half g_W16[3][C_*C_];
__device__ float g_k[BTC], g_v[BTC], g_r[BTC];
// scan scratch
__device__ float g_chA[NCH][BC_], g_chB[NCH][BC_], g_chP[NCH][BC_];
__device__ float g_inA[NCH][BC_], g_inB[NCH][BC_], g_inP[NCH][BC_];
__device__ float g_psum[NCH][BC_];
__device__ float g_ylast[BC_];
__device__ float g_z[BC_];

// ---------------------------------------------------------------------------
// Generic-PTX helpers (sm_80-class; safe for the harness's compute_103 build)
// ---------------------------------------------------------------------------
__device__ __forceinline__ uint32_t smem_u32(const void* p) {
    uint32_t a;
    asm("{ .reg .u64 t; cvta.to.shared.u64 t, %1; cvt.u32.u64 %0, t; }" : "=r"(a) : "l"(p));
    return a;
}
__device__ __forceinline__ void cpa16(uint32_t dst, const void* src) {
    asm volatile("cp.async.cg.shared.global [%0], [%1], 16;\n" :: "r"(dst), "l"(src));
}
__device__ __forceinline__ void cpa_commit() {
    asm volatile("cp.async.commit_group;\n" ::: "memory");
}
__device__ __forceinline__ void cpa_wait1() {
    asm volatile("cp.async.wait_group 1;\n" ::: "memory");
}
__device__ __forceinline__ void cpa_wait0() {
    asm volatile("cp.async.wait_group 0;\n" ::: "memory");
}
__device__ __forceinline__ void ldsm_x4(uint32_t& r0, uint32_t& r1, uint32_t& r2, uint32_t& r3,
                                        uint32_t addr) {
    asm volatile("ldmatrix.sync.aligned.m8n8.x4.shared.b16 {%0,%1,%2,%3}, [%4];"
                 : "=r"(r0), "=r"(r1), "=r"(r2), "=r"(r3) : "r"(addr));
}
__device__ __forceinline__ void ldsm_x2(uint32_t& r0, uint32_t& r1, uint32_t addr) {
    asm volatile("ldmatrix.sync.aligned.m8n8.x2.shared.b16 {%0,%1}, [%2];"
                 : "=r"(r0), "=r"(r1) : "r"(addr));
}
__device__ __forceinline__ void mma16816(float& d0, float& d1, float& d2, float& d3,
                                         uint32_t a0, uint32_t a1, uint32_t a2, uint32_t a3,
                                         uint32_t b0, uint32_t b1) {
    asm volatile(
        "mma.sync.aligned.m16n8k16.row.col.f32.f16.f16.f32 "
        "{%0,%1,%2,%3}, {%4,%5,%6,%7}, {%8,%9}, {%0,%1,%2,%3};"
        : "+f"(d0), "+f"(d1), "+f"(d2), "+f"(d3)
        : "r"(a0), "r"(a1), "r"(a2), "r"(a3), "r"(b0), "r"(b1));
}

// ---------------------------------------------------------------------------
// K0: weights fp32 -> fp16
// ---------------------------------------------------------------------------
__global__ __launch_bounds__(256)
void conv_w_kernel(const float* __restrict__ Wk,
                   const float* __restrict__ Wv,
                   const float* __restrict__ Wr)
{
    int which = blockIdx.y;
    int i = blockIdx.x * 256 + threadIdx.x;
    const float* src = (which == 0) ? Wk : (which == 1) ? Wv : Wr;
    g_W16[which][i] = __float2half_rn(src[i]);
}

// ---------------------------------------------------------------------------
// K1: embedding gather + time-mix -> hi/lo fp16, vectorized x2 (half2 stores)
// ---------------------------------------------------------------------------
__global__ __launch_bounds__(256)
void embed_mix_kernel(const int*   __restrict__ tok,
                      const float* __restrict__ xx_init,
                      const float* __restrict__ emb,
                      const float* __restrict__ tmk,
                      const float* __restrict__ tmv,
                      const float* __restrict__ tmr)
{
    int idx2 = blockIdx.x * blockDim.x + threadIdx.x;   // < BTC/2
    int c2 = idx2 & 511;
    int bt = idx2 >> 9;
    int t  = bt & (T_ - 1);
    int b  = bt >> 11;
    int c  = c2 * 2;

    int token = tok[bt];
    float2 xc = *(const float2*)&emb[token * C_ + c];
    float2 xp;
    if (t == 0) xp = *(const float2*)&xx_init[b * C_ + c];
    else        xp = *(const float2*)&emb[tok[bt - 1] * C_ + c];

    float2 mk = *(const float2*)&tmk[c];
    float2 mv = *(const float2*)&tmv[c];
    float2 mr = *(const float2*)&tmr[c];

#define SPLIT_STORE(hiArr, loArr, m)  do {                                  \
        float v0 = xc.x * (m).x + xp.x * (1.0f - (m).x);                    \
        float v1 = xc.y * (m).y + xp.y * (1.0f - (m).y);                    \
        __half h0 = __float2half_rn(v0), h1 = __float2half_rn(v1);          \
        __half l0 = __float2half_rn(v0 - __half2float(h0));                 \
        __half l1 = __float2half_rn(v1 - __half2float(h1));                 \
        reinterpret_cast<__half2*>(hiArr)[idx2] = __halves2half2(h0, h1);   \
        reinterpret_cast<__half2*>(loArr)[idx2] = __halves2half2(l0, l1);   \
    } while (0)

    SPLIT_STORE(g_xk_hi, g_xk_lo, mk);
    SPLIT_STORE(g_xv_hi, g_xv_lo, mv);
    SPLIT_STORE(g_xr_hi, g_xr_lo, mr);
#undef SPLIT_STORE
}

// ---------------------------------------------------------------------------
// K2: 2-term fp16 split NT GEMM: C = Ahi*W + Alo*W (A = Ahi+Alo exactly).
// Tiles: 128x256x32, 8 warps (warp tile 64x64), 3-stage cp.async pipeline.
// SMEM rows padded to 80B => conflict-free ldmatrix.
// blockIdx.z: 0 -> k, 1 -> v, 2 -> sigmoid -> r
// ---------------------------------------------------------------------------
#define BM 128
#define BN 256
#define BK 32
#define ROWB 80
#define AT_BYTES (BM * ROWB)             // 10240 per A tile (hi or lo)
#define BT_BYTES (BN * ROWB)             // 20480 for W tile
#define STAGEB (2*AT_BYTES + BT_BYTES)   // 40960
#define NSTAGE 3
#define GEMM_SMEM (NSTAGE * STAGEB)      // 122880
#define NKT (C_ / BK)                    // 32 K-chunks

__global__ __launch_bounds__(256, 1)
void gemm_mma_kernel()
{
    extern __shared__ char smem[];
    const uint32_t sb = smem_u32(smem);
    const int tid  = threadIdx.x;
    const int wid  = tid >> 5;
    const int lane = tid & 31;

    const int which = blockIdx.z;
    const int n0 = blockIdx.x * BN;
    const int m0 = blockIdx.y * BM;

    const __half* Ahi = (which == 0) ? g_xk_hi : (which == 1) ? g_xv_hi : g_xr_hi;
    const __half* Alo = (which == 0) ? g_xk_lo : (which == 1) ? g_xv_lo : g_xr_lo;
    const __half* Wp  = g_W16[which];
    float* __restrict__ Cout = (which == 0) ? g_k : (which == 1) ? g_v : g_r;

    const char* Ahi_g = (const char*)(Ahi + (size_t)m0 * C_);
    const char* Alo_g = (const char*)(Alo + (size_t)m0 * C_);
    const char* W_g   = (const char*)(Wp  + (size_t)n0 * C_);

    const int warp_m = (wid & 1) * 64;   // 2 warps along M
    const int warp_n = (wid >> 1) * 64;  // 4 warps along N

    float acc[4][8][4];
#pragma unroll
    for (int i = 0; i < 4; i++)
#pragma unroll
        for (int j = 0; j < 8; j++)
#pragma unroll
            for (int q = 0; q < 4; q++) acc[i][j][q] = 0.0f;

    // Load one K-chunk: Ahi, Alo (128 rows x 64B), W (256 rows x 64B)
    auto issue_stage = [&](int kt, int stg) {
        const int kb = kt * BK * 2;              // byte offset along K
        uint32_t base = sb + stg * STAGEB;
        // A granules: 2 tiles x 128 rows x 4 x16B = 1024
        for (int g = tid; g < 1024; g += 256) {
            int t = g >> 9;
            int r = (g >> 2) & 127;
            int c = g & 3;
            const char* src = (t ? Alo_g : Ahi_g) + (size_t)r * (C_ * 2) + kb + c * 16;
            cpa16(base + t * AT_BYTES + r * ROWB + c * 16, src);
        }
        // W granules: 256 rows x 4 x16B = 1024
        for (int g = tid; g < 1024; g += 256) {
            int r = g >> 2;
            int c = g & 3;
            const char* src = W_g + (size_t)r * (C_ * 2) + kb + c * 16;
            cpa16(base + 2 * AT_BYTES + r * ROWB + c * 16, src);
        }
        cpa_commit();
    };

    issue_stage(0, 0);
    issue_stage(1, 1);

    const int l15 = lane & 15;
    const int l7  = lane & 7;

    for (int kt = 0; kt < NKT; kt++) {
        if (kt == NKT - 1) cpa_wait0(); else cpa_wait1();
        __syncthreads();
        if (kt + 2 < NKT) issue_stage(kt + 2, (kt + 2) % NSTAGE);

        const uint32_t base = sb + (kt % NSTAGE) * STAGEB;
        const uint32_t ah = base;
        const uint32_t al = base + AT_BYTES;
        const uint32_t bw = base + 2 * AT_BYTES;

#pragma unroll
        for (int ks = 0; ks < 2; ks++) {
            uint32_t ahi_f[4][4], alo_f[4][4];
            uint32_t bf[8][2];
            const uint32_t arow = (warp_m + l15) * ROWB + ks * 32 + (lane >> 4) * 16;
#pragma unroll
            for (int mt = 0; mt < 4; mt++) {
                ldsm_x4(ahi_f[mt][0], ahi_f[mt][1], ahi_f[mt][2], ahi_f[mt][3],
                        ah + arow + mt * (16 * ROWB));
                ldsm_x4(alo_f[mt][0], alo_f[mt][1], alo_f[mt][2], alo_f[mt][3],
                        al + arow + mt * (16 * ROWB));
            }
            const uint32_t brow = (warp_n + l7) * ROWB + ks * 32 + ((lane >> 3) & 1) * 16;
#pragma unroll
            for (int nt = 0; nt < 8; nt++)
                ldsm_x2(bf[nt][0], bf[nt][1], bw + brow + nt * (8 * ROWB));
#pragma unroll
            for (int mt = 0; mt < 4; mt++)
#pragma unroll
                for (int nt = 0; nt < 8; nt++)
                    mma16816(acc[mt][nt][0], acc[mt][nt][1], acc[mt][nt][2], acc[mt][nt][3],
                             ahi_f[mt][0], ahi_f[mt][1], ahi_f[mt][2], ahi_f[mt][3],
                             bf[nt][0], bf[nt][1]);
#pragma unroll
            for (int mt = 0; mt < 4; mt++)
#pragma unroll
                for (int nt = 0; nt < 8; nt++)
                    mma16816(acc[mt][nt][0], acc[mt][nt][1], acc[mt][nt][2], acc[mt][nt][3],
                             alo_f[mt][0], alo_f[mt][1], alo_f[mt][2], alo_f[mt][3],
                             bf[nt][0], bf[nt][1]);
        }
        __syncthreads();
    }

    // ---- epilogue: direct register -> global stores
    const int rbase = m0 + warp_m + (lane >> 2);
    const int cbase = n0 + warp_n + (lane & 3) * 2;
#pragma unroll
    for (int mt = 0; mt < 4; mt++) {
#pragma unroll
        for (int nt = 0; nt < 8; nt++) {
            float v0 = acc[mt][nt][0], v1 = acc[mt][nt][1];
            float v2 = acc[mt][nt][2], v3 = acc[mt][nt][3];
            if (which == 2) {
                v0 = 1.0f / (1.0f + __expf(-v0));
                v1 = 1.0f / (1.0f + __expf(-v1));
                v2 = 1.0f / (1.0f + __expf(-v2));
                v3 = 1.0f / (1.0f + __expf(-v3));
            }
            size_t r0 = (size_t)(rbase + mt * 16) * C_ + cbase + nt * 8;
            size_t r1 = r0 + 8 * C_;
            *(float2*)&Cout[r0] = make_float2(v0, v1);
            *(float2*)&Cout[r1] = make_float2(v2, v3);
        }
    }
}

// ---------------------------------------------------------------------------
// K3a: chunk-local WKV state summaries (A, B, P) — 16 chunks x 8192 channels.
// Unnormalized recurrence with running-max stabilization, empty-state init.
// ---------------------------------------------------------------------------
__global__ __launch_bounds__(256)
void wkv_passA(const float* __restrict__ time_decay)
{
    const int tid = blockIdx.x * blockDim.x + threadIdx.x;  // 0..131071
    const int bc = tid & (BC_ - 1);
    const int j  = tid >> 13;
    const int c  = bc & (C_ - 1);
    const int b  = bc >> 10;

    const float w = -expf(time_decay[c]);
    float aa = 0.0f, bb = 0.0f, pp = -1e30f;

    const int base = (b * T_ + j * CL) * C_ + c;
#pragma unroll 4
    for (int i = 0; i < CL; i++) {
        float kt = g_k[base + i * C_];
        float vt = g_v[base + i * C_];
        float ww2 = pp + w;
        float d2  = ww2 - kt;
        float es  = __expf(-fabsf(d2));
        float e1  = (d2 >= 0.0f) ? 1.0f : es;
        float e2  = (d2 >= 0.0f) ? es : 1.0f;
        aa = e1 * aa + e2 * vt;
        bb = e1 * bb + e2;
        pp = fmaxf(ww2, kt);
    }
    g_chA[j][bc] = aa;
    g_chB[j][bc] = bb;
    g_chP[j][bc] = pp;
}

// ---------------------------------------------------------------------------
// K3b: serial compose over 16 chunk summaries -> incoming state per chunk.
// ---------------------------------------------------------------------------
__global__ __launch_bounds__(256)
void wkv_passB(const float* __restrict__ aa_init,
               const float* __restrict__ bb_init,
               const float* __restrict__ pp_init,
               const float* __restrict__ time_decay)
{
    const int bc = blockIdx.x * blockDim.x + threadIdx.x;  // 0..8191
    const int c  = bc & (C_ - 1);

    float aa = aa_init[bc], bb = bb_init[bc], pp = pp_init[bc];
    const float Lw = (float)CL * (-expf(time_decay[c]));

#pragma unroll
    for (int j = 0; j < NCH; j++) {
        g_inA[j][bc] = aa;
        g_inB[j][bc] = bb;
        g_inP[j][bc] = pp;
        float q  = pp + Lw;
        float Pj = g_chP[j][bc];
        float Aj = g_chA[j][bc];
        float Bj = g_chB[j][bc];
        float Pn = fmaxf(q, Pj);
        float e1 = __expf(q - Pn);
        float e2 = __expf(Pj - Pn);
        aa = e1 * aa + e2 * Aj;
        bb = e1 * bb + e2 * Bj;
        pp = Pn;
    }
}

// ---------------------------------------------------------------------------
// K3c: replay each chunk with its incoming state; emit partial ysum + ylast.
// ---------------------------------------------------------------------------
__global__ __launch_bounds__(256)
void wkv_passC(const float* __restrict__ time_decay,
               const float* __restrict__ time_first)
{
    const int tid = blockIdx.x * blockDim.x + threadIdx.x;  // 0..131071
    const int bc = tid & (BC_ - 1);
    const int j  = tid >> 13;
    const int c  = bc & (C_ - 1);
    const int b  = bc >> 10;

    const float w = -expf(time_decay[c]);
    const float u = time_first[c];

    float aa = g_inA[j][bc];
    float bb = g_inB[j][bc];
    float pp = g_inP[j][bc];

    float ysum = 0.0f;
    float y = 0.0f;

    const int base = (b * T_ + j * CL) * C_ + c;
#pragma unroll 4
    for (int i = 0; i < CL; i++) {
        float kt = g_k[base + i * C_];
        float vt = g_v[base + i * C_];
        float rt = g_r[base + i * C_];
        float ww = u + kt;
        float d  = pp - ww;
        float es = __expf(-fabsf(d));
        float e1 = (d >= 0.0f) ? 1.0f : es;
        float e2 = (d >= 0.0f) ? es : 1.0f;
        y = rt * __fdividef(e1 * aa + e2 * vt, e1 * bb + e2);
        ysum += y;
        float ww2 = pp + w;
        float d2  = ww2 - kt;
        float es2 = __expf(-fabsf(d2));
        float e1b = (d2 >= 0.0f) ? 1.0f : es2;
        float e2b = (d2 >= 0.0f) ? es2 : 1.0f;
        aa = e1b * aa + e2b * vt;
        bb = e1b * bb + e2b;
        pp = fmaxf(ww2, kt);
    }
    g_psum[j][bc] = ysum;
    if (j == NCH - 1) g_ylast[bc] = y;
}

// ---------------------------------------------------------------------------
// K3d: reduce partials -> z = 0.5*(ylast + mean)
// ---------------------------------------------------------------------------
__global__ __launch_bounds__(256)
void wkv_reduce()
{
    const int bc = blockIdx.x * blockDim.x + threadIdx.x;  // 0..8191
    float s = 0.0f;
#pragma unroll
    for (int j = 0; j < NCH; j++) s += g_psum[j][bc];
    g_z[bc] = 0.5f * (g_ylast[bc] + s * (1.0f / (float)T_));
}

// ---------------------------------------------------------------------------
// K4: tiny output GEMM hx[b,d] = sum_c z[b,c] * Wo[d,c]; out = stack([hx,hx])
// ---------------------------------------------------------------------------
__global__ __launch_bounds__(256)
void final_proj_kernel(const float* __restrict__ Wo,
                       float* __restrict__ out)
{
    int gw   = (blockIdx.x * blockDim.x + threadIdx.x) >> 5;
    int lane = threadIdx.x & 31;
    if (gw >= BC_) return;
    int b = gw >> 10;
    int d = gw & (C_ - 1);

    const float* z  = g_z + b * C_;
    const float* wr = Wo + (size_t)d * C_;
    float s = 0.0f;
#pragma unroll 8
    for (int c = lane; c < C_; c += 32)
        s = fmaf(z[c], wr[c], s);
#pragma unroll
    for (int o = 16; o > 0; o >>= 1)
        s += __shfl_xor_sync(0xFFFFFFFFu, s, o);
    if (lane == 0) {
        out[b * C_ + d]           = s;
        out[BC_ + b * C_ + d]     = s;
    }
}

// ---------------------------------------------------------------------------
extern "C" void kernel_launch(void* const* d_in, const int* in_sizes, int n_in,
                              void* d_out, int out_size)
{
    const int*   tok  = (const int*)  d_in[0];
    const float* xx   = (const float*)d_in[1];
    const float* aa   = (const float*)d_in[2];
    const float* bb   = (const float*)d_in[3];
    const float* pp   = (const float*)d_in[4];
    const float* emb  = (const float*)d_in[5];
    const float* tmk  = (const float*)d_in[6];
    const float* tmv  = (const float*)d_in[7];
    const float* tmr  = (const float*)d_in[8];
    const float* tdec = (const float*)d_in[9];
    const float* tfir = (const float*)d_in[10];
    const float* Wk   = (const float*)d_in[11];
    const float* Wv   = (const float*)d_in[12];
    const float* Wr   = (const float*)d_in[13];
    const float* Wo   = (const float*)d_in[14];
    float* out = (float*)d_out;

    cudaFuncSetAttribute(gemm_mma_kernel,
                         cudaFuncAttributeMaxDynamicSharedMemorySize, GEMM_SMEM);

    dim3 wgrid(C_ * C_ / 256, 3);
    conv_w_kernel<<<wgrid, 256>>>(Wk, Wv, Wr);

    embed_mix_kernel<<<BTC / 2 / 256, 256>>>(tok, xx, emb, tmk, tmv, tmr);

    dim3 ggrid(C_ / BN, M_ / BM, 3);   // (4, 128, 3)
    gemm_mma_kernel<<<ggrid, 256, GEMM_SMEM>>>();

    wkv_passA<<<(NCH * BC_) / 256, 256>>>(tdec);
    wkv_passB<<<BC_ / 256, 256>>>(aa, bb, pp, tdec);
    wkv_passC<<<(NCH * BC_) / 256, 256>>>(tdec, tfir);
    wkv_reduce<<<BC_ / 256, 256>>>();

    final_proj_kernel<<<(BC_ * 32) / 256, 256>>>(Wo, out);
}

// round 6
// speedup vs baseline: 3.5310x; 1.0263x over previous
#include <cuda_runtime.h>
#include <cuda_fp16.h>
#include <cstdint>
#include <cmath>

// Problem constants
#define B_   8
#define T_   2048
#define C_   1024
#define M_   (B_*T_)       // 16384
#define BTC  (B_*T_*C_)    // 16777216
#define BC_  (B_*C_)       // 8192

// Chunked scan
#define NCH 16
#define CL  (T_/NCH)       // 128

// ---------------------------------------------------------------------------
// Scratch (__device__ globals; no cudaMalloc allowed)
// ---------------------------------------------------------------------------
__device__ __half g_xk_hi[BTC], g_xk_lo[BTC];
__device__ __half g_xv_hi[BTC], g_xv_lo[BTC];
__device__ __half g_xr_hi[BTC], g_xr_lo[BTC];
__device__ __half g_W16[3][C_*C_];
__device__ float g_k[BTC], g_v[BTC], g_r[BTC];
// scan scratch
__device__ float g_chA[NCH][BC_], g_chB[NCH][BC_], g_chP[NCH][BC_];
__device__ float g_inA[NCH][BC_], g_inB[NCH][BC_], g_inP[NCH][BC_];
__device__ float g_psum[NCH][BC_];
__device__ float g_ylast[BC_];
__device__ float g_z[BC_];

// ---------------------------------------------------------------------------
// Generic-PTX helpers (sm_80-class; safe for the harness's compute_103 build)
// ---------------------------------------------------------------------------
__device__ __forceinline__ uint32_t smem_u32(const void* p) {
    uint32_t a;
    asm("{ .reg .u64 t; cvta.to.shared.u64 t, %1; cvt.u32.u64 %0, t; }" : "=r"(a) : "l"(p));
    return a;
}
__device__ __forceinline__ void cpa16(uint32_t dst, const void* src) {
    asm volatile("cp.async.cg.shared.global [%0], [%1], 16;\n" :: "r"(dst), "l"(src));
}
__device__ __forceinline__ void cpa_commit() {
    asm volatile("cp.async.commit_group;\n" ::: "memory");
}
__device__ __forceinline__ void cpa_wait1() {
    asm volatile("cp.async.wait_group 1;\n" ::: "memory");
}
__device__ __forceinline__ void cpa_wait0() {
    asm volatile("cp.async.wait_group 0;\n" ::: "memory");
}
__device__ __forceinline__ void ldsm_x4(uint32_t& r0, uint32_t& r1, uint32_t& r2, uint32_t& r3,
                                        uint32_t addr) {
    asm volatile("ldmatrix.sync.aligned.m8n8.x4.shared.b16 {%0,%1,%2,%3}, [%4];"
                 : "=r"(r0), "=r"(r1), "=r"(r2), "=r"(r3) : "r"(addr));
}
// fp32-accumulate fp16 MMA (hi term)
__device__ __forceinline__ void mma16816(float& d0, float& d1, float& d2, float& d3,
                                         uint32_t a0, uint32_t a1, uint32_t a2, uint32_t a3,
                                         uint32_t b0, uint32_t b1) {
    asm volatile(
        "mma.sync.aligned.m16n8k16.row.col.f32.f16.f16.f32 "
        "{%0,%1,%2,%3}, {%4,%5,%6,%7}, {%8,%9}, {%0,%1,%2,%3};"
        : "+f"(d0), "+f"(d1), "+f"(d2), "+f"(d3)
        : "r"(a0), "r"(a1), "r"(a2), "r"(a3), "r"(b0), "r"(b1));
}
// fp16-accumulate fp16 MMA (lo term; values are ~2^-11 scale => f16 rounding safe)
__device__ __forceinline__ void mma16816_h(uint32_t& d0, uint32_t& d1,
                                           uint32_t a0, uint32_t a1, uint32_t a2, uint32_t a3,
                                           uint32_t b0, uint32_t b1) {
    asm volatile(
        "mma.sync.aligned.m16n8k16.row.col.f16.f16.f16.f16 "
        "{%0,%1}, {%2,%3,%4,%5}, {%6,%7}, {%0,%1};"
        : "+r"(d0), "+r"(d1)
        : "r"(a0), "r"(a1), "r"(a2), "r"(a3), "r"(b0), "r"(b1));
}

// ---------------------------------------------------------------------------
// K0: weights fp32 -> fp16
// ---------------------------------------------------------------------------
__global__ __launch_bounds__(256)
void conv_w_kernel(const float* __restrict__ Wk,
                   const float* __restrict__ Wv,
                   const float* __restrict__ Wr)
{
    int which = blockIdx.y;
    int i = blockIdx.x * 256 + threadIdx.x;
    const float* src = (which == 0) ? Wk : (which == 1) ? Wv : Wr;
    g_W16[which][i] = __float2half_rn(src[i]);
}

// ---------------------------------------------------------------------------
// K1: embedding gather + time-mix -> hi/lo fp16, vectorized x2 (half2 stores)
// ---------------------------------------------------------------------------
__global__ __launch_bounds__(256)
void embed_mix_kernel(const int*   __restrict__ tok,
                      const float* __restrict__ xx_init,
                      const float* __restrict__ emb,
                      const float* __restrict__ tmk,
                      const float* __restrict__ tmv,
                      const float* __restrict__ tmr)
{
    int idx2 = blockIdx.x * blockDim.x + threadIdx.x;   // < BTC/2
    int c2 = idx2 & 511;
    int bt = idx2 >> 9;
    int t  = bt & (T_ - 1);
    int b  = bt >> 11;
    int c  = c2 * 2;

    int token = tok[bt];
    float2 xc = *(const float2*)&emb[token * C_ + c];
    float2 xp;
    if (t == 0) xp = *(const float2*)&xx_init[b * C_ + c];
    else        xp = *(const float2*)&emb[tok[bt - 1] * C_ + c];

    float2 mk = *(const float2*)&tmk[c];
    float2 mv = *(const float2*)&tmv[c];
    float2 mr = *(const float2*)&tmr[c];

#define SPLIT_STORE(hiArr, loArr, m)  do {                                  \
        float v0 = xc.x * (m).x + xp.x * (1.0f - (m).x);                    \
        float v1 = xc.y * (m).y + xp.y * (1.0f - (m).y);                    \
        __half h0 = __float2half_rn(v0), h1 = __float2half_rn(v1);          \
        __half l0 = __float2half_rn(v0 - __half2float(h0));                 \
        __half l1 = __float2half_rn(v1 - __half2float(h1));                 \
        reinterpret_cast<__half2*>(hiArr)[idx2] = __halves2half2(h0, h1);   \
        reinterpret_cast<__half2*>(loArr)[idx2] = __halves2half2(l0, l1);   \
    } while (0)

    SPLIT_STORE(g_xk_hi, g_xk_lo, mk);
    SPLIT_STORE(g_xv_hi, g_xv_lo, mv);
    SPLIT_STORE(g_xr_hi, g_xr_lo, mr);
#undef SPLIT_STORE
}

// ---------------------------------------------------------------------------
// K2: 2-term fp16 split NT GEMM: C = Ahi*W (f32 acc) + Alo*W (f16 acc).
// Tiles: 128x256x32, 8 warps (warp tile 64x64), 3-stage cp.async pipeline,
// one barrier per K-chunk. SMEM rows padded to 80B => conflict-free ldmatrix.
// blockIdx.z: 0 -> k, 1 -> v, 2 -> sigmoid -> r
// ---------------------------------------------------------------------------
#define BM 128
#define BN 256
#define BK 32
#define ROWB 80
#define AT_BYTES (BM * ROWB)             // 10240 per A tile (hi or lo)
#define BT_BYTES (BN * ROWB)             // 20480 for W tile
#define STAGEB (2*AT_BYTES + BT_BYTES)   // 40960
#define NSTAGE 3
#define GEMM_SMEM (NSTAGE * STAGEB)      // 122880
#define NKT (C_ / BK)                    // 32 K-chunks

__global__ __launch_bounds__(256, 1)
void gemm_mma_kernel()
{
    extern __shared__ char smem[];
    const uint32_t sb = smem_u32(smem);
    const int tid  = threadIdx.x;
    const int wid  = tid >> 5;
    const int lane = tid & 31;

    const int which = blockIdx.z;
    const int n0 = blockIdx.x * BN;
    const int m0 = blockIdx.y * BM;

    const __half* Ahi = (which == 0) ? g_xk_hi : (which == 1) ? g_xv_hi : g_xr_hi;
    const __half* Alo = (which == 0) ? g_xk_lo : (which == 1) ? g_xv_lo : g_xr_lo;
    const __half* Wp  = g_W16[which];
    float* __restrict__ Cout = (which == 0) ? g_k : (which == 1) ? g_v : g_r;

    const char* Ahi_g = (const char*)(Ahi + (size_t)m0 * C_);
    const char* Alo_g = (const char*)(Alo + (size_t)m0 * C_);
    const char* W_g   = (const char*)(Wp  + (size_t)n0 * C_);

    const int warp_m = (wid & 1) * 64;   // 2 warps along M
    const int warp_n = (wid >> 1) * 64;  // 4 warps along N

    float acc[4][8][4];
    uint32_t accl[4][8][2];              // f16x2 accumulators for the lo term
#pragma unroll
    for (int i = 0; i < 4; i++)
#pragma unroll
        for (int j = 0; j < 8; j++) {
#pragma unroll
            for (int q = 0; q < 4; q++) acc[i][j][q] = 0.0f;
            accl[i][j][0] = 0u; accl[i][j][1] = 0u;
        }

    // Load one K-chunk: Ahi, Alo (128 rows x 64B), W (256 rows x 64B)
    auto issue_stage = [&](int kt, int stg) {
        const int kb = kt * BK * 2;              // byte offset along K
        uint32_t base = sb + stg * STAGEB;
        for (int g = tid; g < 1024; g += 256) {  // A: 2 tiles x 128 x 4
            int t = g >> 9;
            int r = (g >> 2) & 127;
            int c = g & 3;
            const char* src = (t ? Alo_g : Ahi_g) + (size_t)r * (C_ * 2) + kb + c * 16;
            cpa16(base + t * AT_BYTES + r * ROWB + c * 16, src);
        }
        for (int g = tid; g < 1024; g += 256) {  // W: 256 x 4
            int r = g >> 2;
            int c = g & 3;
            const char* src = W_g + (size_t)r * (C_ * 2) + kb + c * 16;
            cpa16(base + 2 * AT_BYTES + r * ROWB + c * 16, src);
        }
        cpa_commit();
    };

    issue_stage(0, 0);
    issue_stage(1, 1);

    const int l15 = lane & 15;
    const int l7  = lane & 7;
    // B ldsm_x4 lane mapping: group g = lane>>3 -> row+ (g>>1)*8, koff (g&1)*16
    const int b_rowadd = ((lane >> 4) & 1) * 8 + l7;
    const int b_koff   = ((lane >> 3) & 1) * 16;

    for (int kt = 0; kt < NKT; kt++) {
        if (kt == NKT - 1) cpa_wait0(); else cpa_wait1();
        __syncthreads();
        if (kt + 2 < NKT) issue_stage(kt + 2, (kt + 2) % NSTAGE);

        const uint32_t base = sb + (kt % NSTAGE) * STAGEB;
        const uint32_t ah = base;
        const uint32_t al = base + AT_BYTES;
        const uint32_t bw = base + 2 * AT_BYTES;

#pragma unroll
        for (int ks = 0; ks < 2; ks++) {
            uint32_t ahi_f[4][4], alo_f[4][4];
            uint32_t bf[8][2];
            const uint32_t arow = (warp_m + l15) * ROWB + ks * 32 + (lane >> 4) * 16;
#pragma unroll
            for (int mt = 0; mt < 4; mt++) {
                ldsm_x4(ahi_f[mt][0], ahi_f[mt][1], ahi_f[mt][2], ahi_f[mt][3],
                        ah + arow + mt * (16 * ROWB));
                ldsm_x4(alo_f[mt][0], alo_f[mt][1], alo_f[mt][2], alo_f[mt][3],
                        al + arow + mt * (16 * ROWB));
            }
            // B: 4 x ldsm_x4, each covering an nt pair
#pragma unroll
            for (int p = 0; p < 4; p++) {
                uint32_t addr = bw + (warp_n + p * 16 + b_rowadd) * ROWB + ks * 32 + b_koff;
                ldsm_x4(bf[2*p][0], bf[2*p][1], bf[2*p+1][0], bf[2*p+1][1], addr);
            }
#pragma unroll
            for (int mt = 0; mt < 4; mt++)
#pragma unroll
                for (int nt = 0; nt < 8; nt++)
                    mma16816(acc[mt][nt][0], acc[mt][nt][1], acc[mt][nt][2], acc[mt][nt][3],
                             ahi_f[mt][0], ahi_f[mt][1], ahi_f[mt][2], ahi_f[mt][3],
                             bf[nt][0], bf[nt][1]);
#pragma unroll
            for (int mt = 0; mt < 4; mt++)
#pragma unroll
                for (int nt = 0; nt < 8; nt++)
                    mma16816_h(accl[mt][nt][0], accl[mt][nt][1],
                               alo_f[mt][0], alo_f[mt][1], alo_f[mt][2], alo_f[mt][3],
                               bf[nt][0], bf[nt][1]);
        }
    }

    // ---- epilogue: merge f16 lo accumulators, store direct to global
    const int rbase = m0 + warp_m + (lane >> 2);
    const int cbase = n0 + warp_n + (lane & 3) * 2;
#pragma unroll
    for (int mt = 0; mt < 4; mt++) {
#pragma unroll
        for (int nt = 0; nt < 8; nt++) {
            float2 lo01 = __half22float2(*reinterpret_cast<__half2*>(&accl[mt][nt][0]));
            float2 lo23 = __half22float2(*reinterpret_cast<__half2*>(&accl[mt][nt][1]));
            float v0 = acc[mt][nt][0] + lo01.x;
            float v1 = acc[mt][nt][1] + lo01.y;
            float v2 = acc[mt][nt][2] + lo23.x;
            float v3 = acc[mt][nt][3] + lo23.y;
            if (which == 2) {
                v0 = 1.0f / (1.0f + __expf(-v0));
                v1 = 1.0f / (1.0f + __expf(-v1));
                v2 = 1.0f / (1.0f + __expf(-v2));
                v3 = 1.0f / (1.0f + __expf(-v3));
            }
            size_t r0 = (size_t)(rbase + mt * 16) * C_ + cbase + nt * 8;
            size_t r1 = r0 + 8 * C_;
            *(float2*)&Cout[r0] = make_float2(v0, v1);
            *(float2*)&Cout[r1] = make_float2(v2, v3);
        }
    }
}

// ---------------------------------------------------------------------------
// K3a: chunk-local WKV state summaries (A, B, P) — 16 chunks x 8192 channels.
// ---------------------------------------------------------------------------
__global__ __launch_bounds__(256)
void wkv_passA(const float* __restrict__ time_decay)
{
    const int tid = blockIdx.x * blockDim.x + threadIdx.x;  // 0..131071
    const int bc = tid & (BC_ - 1);
    const int j  = tid >> 13;
    const int c  = bc & (C_ - 1);
    const int b  = bc >> 10;

    const float w = -expf(time_decay[c]);
    float aa = 0.0f, bb = 0.0f, pp = -1e30f;

    const int base = (b * T_ + j * CL) * C_ + c;
#pragma unroll 4
    for (int i = 0; i < CL; i++) {
        float kt = g_k[base + i * C_];
        float vt = g_v[base + i * C_];
        float ww2 = pp + w;
        float d2  = ww2 - kt;
        float es  = __expf(-fabsf(d2));
        float e1  = (d2 >= 0.0f) ? 1.0f : es;
        float e2  = (d2 >= 0.0f) ? es : 1.0f;
        aa = e1 * aa + e2 * vt;
        bb = e1 * bb + e2;
        pp = fmaxf(ww2, kt);
    }
    g_chA[j][bc] = aa;
    g_chB[j][bc] = bb;
    g_chP[j][bc] = pp;
}

// ---------------------------------------------------------------------------
// K3b: serial compose over 16 chunk summaries -> incoming state per chunk.
// ---------------------------------------------------------------------------
__global__ __launch_bounds__(256)
void wkv_passB(const float* __restrict__ aa_init,
               const float* __restrict__ bb_init,
               const float* __restrict__ pp_init,
               const float* __restrict__ time_decay)
{
    const int bc = blockIdx.x * blockDim.x + threadIdx.x;  // 0..8191
    const int c  = bc & (C_ - 1);

    float aa = aa_init[bc], bb = bb_init[bc], pp = pp_init[bc];
    const float Lw = (float)CL * (-expf(time_decay[c]));

#pragma unroll
    for (int j = 0; j < NCH; j++) {
        g_inA[j][bc] = aa;
        g_inB[j][bc] = bb;
        g_inP[j][bc] = pp;
        float q  = pp + Lw;
        float Pj = g_chP[j][bc];
        float Aj = g_chA[j][bc];
        float Bj = g_chB[j][bc];
        float Pn = fmaxf(q, Pj);
        float e1 = __expf(q - Pn);
        float e2 = __expf(Pj - Pn);
        aa = e1 * aa + e2 * Aj;
        bb = e1 * bb + e2 * Bj;
        pp = Pn;
    }
}

// ---------------------------------------------------------------------------
// K3c: replay each chunk with its incoming state; emit partial ysum + ylast.
// ---------------------------------------------------------------------------
__global__ __launch_bounds__(256)
void wkv_passC(const float* __restrict__ time_decay,
               const float* __restrict__ time_first)
{
    const int tid = blockIdx.x * blockDim.x + threadIdx.x;  // 0..131071
    const int bc = tid & (BC_ - 1);
    const int j  = tid >> 13;
    const int c  = bc & (C_ - 1);
    const int b  = bc >> 10;

    const float w = -expf(time_decay[c]);
    const float u = time_first[c];

    float aa = g_inA[j][bc];
    float bb = g_inB[j][bc];
    float pp = g_inP[j][bc];

    float ysum = 0.0f;
    float y = 0.0f;

    const int base = (b * T_ + j * CL) * C_ + c;
#pragma unroll 4
    for (int i = 0; i < CL; i++) {
        float kt = g_k[base + i * C_];
        float vt = g_v[base + i * C_];
        float rt = g_r[base + i * C_];
        float ww = u + kt;
        float d  = pp - ww;
        float es = __expf(-fabsf(d));
        float e1 = (d >= 0.0f) ? 1.0f : es;
        float e2 = (d >= 0.0f) ? es : 1.0f;
        y = rt * __fdividef(e1 * aa + e2 * vt, e1 * bb + e2);
        ysum += y;
        float ww2 = pp + w;
        float d2  = ww2 - kt;
        float es2 = __expf(-fabsf(d2));
        float e1b = (d2 >= 0.0f) ? 1.0f : es2;
        float e2b = (d2 >= 0.0f) ? es2 : 1.0f;
        aa = e1b * aa + e2b * vt;
        bb = e1b * bb + e2b;
        pp = fmaxf(ww2, kt);
    }
    g_psum[j][bc] = ysum;
    if (j == NCH - 1) g_ylast[bc] = y;
}

// ---------------------------------------------------------------------------
// K3d: reduce partials -> z = 0.5*(ylast + mean)
// ---------------------------------------------------------------------------
__global__ __launch_bounds__(256)
void wkv_reduce()
{
    const int bc = blockIdx.x * blockDim.x + threadIdx.x;  // 0..8191
    float s = 0.0f;
#pragma unroll
    for (int j = 0; j < NCH; j++) s += g_psum[j][bc];
    g_z[bc] = 0.5f * (g_ylast[bc] + s * (1.0f / (float)T_));
}

// ---------------------------------------------------------------------------
// K4: tiny output GEMM hx[b,d] = sum_c z[b,c] * Wo[d,c]; out = stack([hx,hx])
// ---------------------------------------------------------------------------
__global__ __launch_bounds__(256)
void final_proj_kernel(const float* __restrict__ Wo,
                       float* __restrict__ out)
{
    int gw   = (blockIdx.x * blockDim.x + threadIdx.x) >> 5;
    int lane = threadIdx.x & 31;
    if (gw >= BC_) return;
    int b = gw >> 10;
    int d = gw & (C_ - 1);

    const float* z  = g_z + b * C_;
    const float* wr = Wo + (size_t)d * C_;
    float s = 0.0f;
#pragma unroll 8
    for (int c = lane; c < C_; c += 32)
        s = fmaf(z[c], wr[c], s);
#pragma unroll
    for (int o = 16; o > 0; o >>= 1)
        s += __shfl_xor_sync(0xFFFFFFFFu, s, o);
    if (lane == 0) {
        out[b * C_ + d]       = s;
        out[BC_ + b * C_ + d] = s;
    }
}

// ---------------------------------------------------------------------------
extern "C" void kernel_launch(void* const* d_in, const int* in_sizes, int n_in,
                              void* d_out, int out_size)
{
    const int*   tok  = (const int*)  d_in[0];
    const float* xx   = (const float*)d_in[1];
    const float* aa   = (const float*)d_in[2];
    const float* bb   = (const float*)d_in[3];
    const float* pp   = (const float*)d_in[4];
    const float* emb  = (const float*)d_in[5];
    const float* tmk  = (const float*)d_in[6];
    const float* tmv  = (const float*)d_in[7];
    const float* tmr  = (const float*)d_in[8];
    const float* tdec = (const float*)d_in[9];
    const float* tfir = (const float*)d_in[10];
    const float* Wk   = (const float*)d_in[11];
    const float* Wv   = (const float*)d_in[12];
    const float* Wr   = (const float*)d_in[13];
    const float* Wo   = (const float*)d_in[14];
    float* out = (float*)d_out;

    cudaFuncSetAttribute(gemm_mma_kernel,
                         cudaFuncAttributeMaxDynamicSharedMemorySize, GEMM_SMEM);

    dim3 wgrid(C_ * C_ / 256, 3);
    conv_w_kernel<<<wgrid, 256>>>(Wk, Wv, Wr);

    embed_mix_kernel<<<BTC / 2 / 256, 256>>>(tok, xx, emb, tmk, tmv, tmr);

    dim3 ggrid(C_ / BN, M_ / BM, 3);   // (4, 128, 3)
    gemm_mma_kernel<<<ggrid, 256, GEMM_SMEM>>>();

    wkv_passA<<<(NCH * BC_) / 256, 256>>>(tdec);
    wkv_passB<<<BC_ / 256, 256>>>(aa, bb, pp, tdec);
    wkv_passC<<<(NCH * BC_) / 256, 256>>>(tdec, tfir);
    wkv_reduce<<<BC_ / 256, 256>>>();

    final_proj_kernel<<<(BC_ * 32) / 256, 256>>>(Wo, out);
}

// round 8
// speedup vs baseline: 5.0492x; 1.4299x over previous
#include <cuda_runtime.h>
#include <cuda_fp16.h>
#include <cstdint>
#include <cmath>

// Problem constants
#define B_   8
#define T_   2048
#define C_   1024
#define M_   (B_*T_)       // 16384
#define BTC  (B_*T_*C_)    // 16777216
#define BC_  (B_*C_)       // 8192

// Chunked scan
#define NCH 16
#define CL  (T_/NCH)       // 128

// ---------------------------------------------------------------------------
// Scratch (__device__ globals; no cudaMalloc allowed)
// ---------------------------------------------------------------------------
__device__ __half g_xk[BTC];
__device__ __half g_xv[BTC];
__device__ __half g_xr[BTC];
__device__ __half g_W16[3][C_*C_];
__device__ float g_k[BTC], g_v[BTC], g_r[BTC];
// scan scratch
__device__ float g_chA[NCH][BC_], g_chB[NCH][BC_], g_chP[NCH][BC_];
__device__ float g_inA[NCH][BC_], g_inB[NCH][BC_], g_inP[NCH][BC_];
__device__ float g_psum[NCH][BC_];
__device__ float g_ylast[BC_];
__device__ float g_z[BC_];

// ---------------------------------------------------------------------------
// Generic-PTX helpers (sm_80-class; safe for the harness's compute_103 build)
// ---------------------------------------------------------------------------
__device__ __forceinline__ uint32_t smem_u32(const void* p) {
    uint32_t a;
    asm("{ .reg .u64 t; cvta.to.shared.u64 t, %1; cvt.u32.u64 %0, t; }" : "=r"(a) : "l"(p));
    return a;
}
__device__ __forceinline__ void cpa16(uint32_t dst, const void* src) {
    asm volatile("cp.async.cg.shared.global [%0], [%1], 16;\n" :: "r"(dst), "l"(src));
}
__device__ __forceinline__ void cpa_commit() {
    asm volatile("cp.async.commit_group;\n" ::: "memory");
}
__device__ __forceinline__ void cpa_wait2() {
    asm volatile("cp.async.wait_group 2;\n" ::: "memory");
}
__device__ __forceinline__ void cpa_wait1() {
    asm volatile("cp.async.wait_group 1;\n" ::: "memory");
}
__device__ __forceinline__ void cpa_wait0() {
    asm volatile("cp.async.wait_group 0;\n" ::: "memory");
}
__device__ __forceinline__ void ldsm_x4(uint32_t& r0, uint32_t& r1, uint32_t& r2, uint32_t& r3,
                                        uint32_t addr) {
    asm volatile("ldmatrix.sync.aligned.m8n8.x4.shared.b16 {%0,%1,%2,%3}, [%4];"
                 : "=r"(r0), "=r"(r1), "=r"(r2), "=r"(r3) : "r"(addr));
}
__device__ __forceinline__ void mma16816(float& d0, float& d1, float& d2, float& d3,
                                         uint32_t a0, uint32_t a1, uint32_t a2, uint32_t a3,
                                         uint32_t b0, uint32_t b1) {
    asm volatile(
        "mma.sync.aligned.m16n8k16.row.col.f32.f16.f16.f32 "
        "{%0,%1,%2,%3}, {%4,%5,%6,%7}, {%8,%9}, {%0,%1,%2,%3};"
        : "+f"(d0), "+f"(d1), "+f"(d2), "+f"(d3)
        : "r"(a0), "r"(a1), "r"(a2), "r"(a3), "r"(b0), "r"(b1));
}

// ---------------------------------------------------------------------------
// K0: weights fp32 -> fp16
// ---------------------------------------------------------------------------
__global__ __launch_bounds__(256)
void conv_w_kernel(const float* __restrict__ Wk,
                   const float* __restrict__ Wv,
                   const float* __restrict__ Wr)
{
    int which = blockIdx.y;
    int i = blockIdx.x * 256 + threadIdx.x;
    const float* src = (which == 0) ? Wk : (which == 1) ? Wv : Wr;
    g_W16[which][i] = __float2half_rn(src[i]);
}

// ---------------------------------------------------------------------------
// K1: embedding gather + time-mix -> fp16 xk, xv, xr (half2 stores)
// ---------------------------------------------------------------------------
__global__ __launch_bounds__(256)
void embed_mix_kernel(const int*   __restrict__ tok,
                      const float* __restrict__ xx_init,
                      const float* __restrict__ emb,
                      const float* __restrict__ tmk,
                      const float* __restrict__ tmv,
                      const float* __restrict__ tmr)
{
    int idx2 = blockIdx.x * blockDim.x + threadIdx.x;   // < BTC/2
    int c2 = idx2 & 511;
    int bt = idx2 >> 9;
    int t  = bt & (T_ - 1);
    int b  = bt >> 11;
    int c  = c2 * 2;

    int token = tok[bt];
    float2 xc = *(const float2*)&emb[token * C_ + c];
    float2 xp;
    if (t == 0) xp = *(const float2*)&xx_init[b * C_ + c];
    else        xp = *(const float2*)&emb[tok[bt - 1] * C_ + c];

    float2 mk = *(const float2*)&tmk[c];
    float2 mv = *(const float2*)&tmv[c];
    float2 mr = *(const float2*)&tmr[c];

#define MIX_STORE(arr, m)  do {                                             \
        float v0 = xc.x * (m).x + xp.x * (1.0f - (m).x);                    \
        float v1 = xc.y * (m).y + xp.y * (1.0f - (m).y);                    \
        reinterpret_cast<__half2*>(arr)[idx2] =                             \
            __halves2half2(__float2half_rn(v0), __float2half_rn(v1));       \
    } while (0)

    MIX_STORE(g_xk, mk);
    MIX_STORE(g_xv, mv);
    MIX_STORE(g_xr, mr);
#undef MIX_STORE
}

// ---------------------------------------------------------------------------
// K2: fp16 NT GEMM: C[M,N] = A[M,K] * W[N,K]^T  (fp32 accumulate).
// Tiles: 128x256x32, 8 warps (warp tile 64x64), 4-stage cp.async pipeline,
// one barrier per K-chunk. SMEM rows padded to 80B => conflict-free ldmatrix.
// blockIdx.z: 0 -> k, 1 -> v, 2 -> sigmoid -> r
// ---------------------------------------------------------------------------
#define BM 128
#define BN 256
#define BK 32
#define ROWB 80
#define AT_BYTES (BM * ROWB)             // 10240 A tile
#define BT_BYTES (BN * ROWB)             // 20480 W tile
#define STAGEB (AT_BYTES + BT_BYTES)     // 30720
#define NSTAGE 4
#define GEMM_SMEM (NSTAGE * STAGEB)      // 122880
#define NKT (C_ / BK)                    // 32 K-chunks

__global__ __launch_bounds__(256, 1)
void gemm_mma_kernel()
{
    extern __shared__ char smem[];
    const uint32_t sb = smem_u32(smem);
    const int tid  = threadIdx.x;
    const int wid  = tid >> 5;
    const int lane = tid & 31;

    const int which = blockIdx.z;
    const int n0 = blockIdx.x * BN;
    const int m0 = blockIdx.y * BM;

    const __half* Ap = (which == 0) ? g_xk : (which == 1) ? g_xv : g_xr;
    const __half* Wp = g_W16[which];
    float* __restrict__ Cout = (which == 0) ? g_k : (which == 1) ? g_v : g_r;

    const char* A_g = (const char*)(Ap + (size_t)m0 * C_);
    const char* W_g = (const char*)(Wp + (size_t)n0 * C_);

    const int warp_m = (wid & 1) * 64;   // 2 warps along M
    const int warp_n = (wid >> 1) * 64;  // 4 warps along N

    float acc[4][8][4];
#pragma unroll
    for (int i = 0; i < 4; i++)
#pragma unroll
        for (int j = 0; j < 8; j++)
#pragma unroll
            for (int q = 0; q < 4; q++) acc[i][j][q] = 0.0f;

    // Load one K-chunk: A (128 rows x 64B), W (256 rows x 64B)
    auto issue_stage = [&](int kt, int stg) {
        const int kb = kt * BK * 2;              // byte offset along K
        uint32_t base = sb + stg * STAGEB;
        for (int g = tid; g < 512; g += 256) {   // A: 128 rows x 4 granules
            int r = g >> 2;
            int c = g & 3;
            cpa16(base + r * ROWB + c * 16, A_g + (size_t)r * (C_ * 2) + kb + c * 16);
        }
        for (int g = tid; g < 1024; g += 256) {  // W: 256 rows x 4 granules
            int r = g >> 2;
            int c = g & 3;
            cpa16(base + AT_BYTES + r * ROWB + c * 16,
                  W_g + (size_t)r * (C_ * 2) + kb + c * 16);
        }
        cpa_commit();
    };

    issue_stage(0, 0);
    issue_stage(1, 1);
    issue_stage(2, 2);

    const int l15 = lane & 15;
    const int l7  = lane & 7;
    const int b_rowadd = ((lane >> 4) & 1) * 8 + l7;
    const int b_koff   = ((lane >> 3) & 1) * 16;

    for (int kt = 0; kt < NKT; kt++) {
        if (kt < NKT - 2)       cpa_wait2();
        else if (kt == NKT - 2) cpa_wait1();
        else                    cpa_wait0();
        __syncthreads();
        if (kt + 3 < NKT) issue_stage(kt + 3, (kt + 3) % NSTAGE);

        const uint32_t base = sb + (kt % NSTAGE) * STAGEB;
        const uint32_t ah = base;
        const uint32_t bw = base + AT_BYTES;

#pragma unroll
        for (int ks = 0; ks < 2; ks++) {
            uint32_t af[4][4];
            uint32_t bf[8][2];
            const uint32_t arow = (warp_m + l15) * ROWB + ks * 32 + (lane >> 4) * 16;
#pragma unroll
            for (int mt = 0; mt < 4; mt++)
                ldsm_x4(af[mt][0], af[mt][1], af[mt][2], af[mt][3],
                        ah + arow + mt * (16 * ROWB));
#pragma unroll
            for (int p = 0; p < 4; p++) {
                uint32_t addr = bw + (warp_n + p * 16 + b_rowadd) * ROWB + ks * 32 + b_koff;
                ldsm_x4(bf[2*p][0], bf[2*p][1], bf[2*p+1][0], bf[2*p+1][1], addr);
            }
#pragma unroll
            for (int mt = 0; mt < 4; mt++)
#pragma unroll
                for (int nt = 0; nt < 8; nt++)
                    mma16816(acc[mt][nt][0], acc[mt][nt][1], acc[mt][nt][2], acc[mt][nt][3],
                             af[mt][0], af[mt][1], af[mt][2], af[mt][3],
                             bf[nt][0], bf[nt][1]);
        }
    }

    // ---- epilogue: direct register -> global stores
    const int rbase = m0 + warp_m + (lane >> 2);
    const int cbase = n0 + warp_n + (lane & 3) * 2;
#pragma unroll
    for (int mt = 0; mt < 4; mt++) {
#pragma unroll
        for (int nt = 0; nt < 8; nt++) {
            float v0 = acc[mt][nt][0], v1 = acc[mt][nt][1];
            float v2 = acc[mt][nt][2], v3 = acc[mt][nt][3];
            if (which == 2) {
                v0 = 1.0f / (1.0f + __expf(-v0));
                v1 = 1.0f / (1.0f + __expf(-v1));
                v2 = 1.0f / (1.0f + __expf(-v2));
                v3 = 1.0f / (1.0f + __expf(-v3));
            }
            size_t r0 = (size_t)(rbase + mt * 16) * C_ + cbase + nt * 8;
            size_t r1 = r0 + 8 * C_;
            *(float2*)&Cout[r0] = make_float2(v0, v1);
            *(float2*)&Cout[r1] = make_float2(v2, v3);
        }
    }
}

// ---------------------------------------------------------------------------
// K3a: chunk-local WKV state summaries (A, B, P) — 16 chunks x 8192 channels.
// ---------------------------------------------------------------------------
__global__ __launch_bounds__(256)
void wkv_passA(const float* __restrict__ time_decay)
{
    const int tid = blockIdx.x * blockDim.x + threadIdx.x;  // 0..131071
    const int bc = tid & (BC_ - 1);
    const int j  = tid >> 13;
    const int c  = bc & (C_ - 1);
    const int b  = bc >> 10;

    const float w = -expf(time_decay[c]);
    float aa = 0.0f, bb = 0.0f, pp = -1e30f;

    const int base = (b * T_ + j * CL) * C_ + c;
#pragma unroll 4
    for (int i = 0; i < CL; i++) {
        float kt = g_k[base + i * C_];
        float vt = g_v[base + i * C_];
        float ww2 = pp + w;
        float d2  = ww2 - kt;
        float es  = __expf(-fabsf(d2));
        float e1  = (d2 >= 0.0f) ? 1.0f : es;
        float e2  = (d2 >= 0.0f) ? es : 1.0f;
        aa = e1 * aa + e2 * vt;
        bb = e1 * bb + e2;
        pp = fmaxf(ww2, kt);
    }
    g_chA[j][bc] = aa;
    g_chB[j][bc] = bb;
    g_chP[j][bc] = pp;
}

// ---------------------------------------------------------------------------
// K3b: serial compose over 16 chunk summaries -> incoming state per chunk.
// ---------------------------------------------------------------------------
__global__ __launch_bounds__(256)
void wkv_passB(const float* __restrict__ aa_init,
               const float* __restrict__ bb_init,
               const float* __restrict__ pp_init,
               const float* __restrict__ time_decay)
{
    const int bc = blockIdx.x * blockDim.x + threadIdx.x;  // 0..8191
    const int c  = bc & (C_ - 1);

    float aa = aa_init[bc], bb = bb_init[bc], pp = pp_init[bc];
    const float Lw = (float)CL * (-expf(time_decay[c]));

#pragma unroll
    for (int j = 0; j < NCH; j++) {
        g_inA[j][bc] = aa;
        g_inB[j][bc] = bb;
        g_inP[j][bc] = pp;
        float q  = pp + Lw;
        float Pj = g_chP[j][bc];
        float Aj = g_chA[j][bc];
        float Bj = g_chB[j][bc];
        float Pn = fmaxf(q, Pj);
        float e1 = __expf(q - Pn);
        float e2 = __expf(Pj - Pn);
        aa = e1 * aa + e2 * Aj;
        bb = e1 * bb + e2 * Bj;
        pp = Pn;
    }
}

// ---------------------------------------------------------------------------
// K3c: replay each chunk with its incoming state; emit partial ysum + ylast.
// ---------------------------------------------------------------------------
__global__ __launch_bounds__(256)
void wkv_passC(const float* __restrict__ time_decay,
               const float* __restrict__ time_first)
{
    const int tid = blockIdx.x * blockDim.x + threadIdx.x;  // 0..131071
    const int bc = tid & (BC_ - 1);
    const int j  = tid >> 13;
    const int c  = bc & (C_ - 1);
    const int b  = bc >> 10;

    const float w = -expf(time_decay[c]);
    const float u = time_first[c];

    float aa = g_inA[j][bc];
    float bb = g_inB[j][bc];
    float pp = g_inP[j][bc];

    float ysum = 0.0f;
    float y = 0.0f;

    const int base = (b * T_ + j * CL) * C_ + c;
#pragma unroll 4
    for (int i = 0; i < CL; i++) {
        float kt = g_k[base + i * C_];
        float vt = g_v[base + i * C_];
        float rt = g_r[base + i * C_];
        float ww = u + kt;
        float d  = pp - ww;
        float es = __expf(-fabsf(d));
        float e1 = (d >= 0.0f) ? 1.0f : es;
        float e2 = (d >= 0.0f) ? es : 1.0f;
        y = rt * __fdividef(e1 * aa + e2 * vt, e1 * bb + e2);
        ysum += y;
        float ww2 = pp + w;
        float d2  = ww2 - kt;
        float es2 = __expf(-fabsf(d2));
        float e1b = (d2 >= 0.0f) ? 1.0f : es2;
        float e2b = (d2 >= 0.0f) ? es2 : 1.0f;
        aa = e1b * aa + e2b * vt;
        bb = e1b * bb + e2b;
        pp = fmaxf(ww2, kt);
    }
    g_psum[j][bc] = ysum;
    if (j == NCH - 1) g_ylast[bc] = y;
}

// ---------------------------------------------------------------------------
// K3d: reduce partials -> z = 0.5*(ylast + mean)
// ---------------------------------------------------------------------------
__global__ __launch_bounds__(256)
void wkv_reduce()
{
    const int bc = blockIdx.x * blockDim.x + threadIdx.x;  // 0..8191
    float s = 0.0f;
#pragma unroll
    for (int j = 0; j < NCH; j++) s += g_psum[j][bc];
    g_z[bc] = 0.5f * (g_ylast[bc] + s * (1.0f / (float)T_));
}

// ---------------------------------------------------------------------------
// K4: tiny output GEMM hx[b,d] = sum_c z[b,c] * Wo[d,c]; out = stack([hx,hx])
// ---------------------------------------------------------------------------
__global__ __launch_bounds__(256)
void final_proj_kernel(const float* __restrict__ Wo,
                       float* __restrict__ out)
{
    int gw   = (blockIdx.x * blockDim.x + threadIdx.x) >> 5;
    int lane = threadIdx.x & 31;
    if (gw >= BC_) return;
    int b = gw >> 10;
    int d = gw & (C_ - 1);

    const float* z  = g_z + b * C_;
    const float* wr = Wo + (size_t)d * C_;
    float s = 0.0f;
#pragma unroll 8
    for (int c = lane; c < C_; c += 32)
        s = fmaf(z[c], wr[c], s);
#pragma unroll
    for (int o = 16; o > 0; o >>= 1)
        s += __shfl_xor_sync(0xFFFFFFFFu, s, o);
    if (lane == 0) {
        out[b * C_ + d]       = s;
        out[BC_ + b * C_ + d] = s;
    }
}

// ---------------------------------------------------------------------------
extern "C" void kernel_launch(void* const* d_in, const int* in_sizes, int n_in,
                              void* d_out, int out_size)
{
    const int*   tok  = (const int*)  d_in[0];
    const float* xx   = (const float*)d_in[1];
    const float* aa   = (const float*)d_in[2];
    const float* bb   = (const float*)d_in[3];
    const float* pp   = (const float*)d_in[4];
    const float* emb  = (const float*)d_in[5];
    const float* tmk  = (const float*)d_in[6];
    const float* tmv  = (const float*)d_in[7];
    const float* tmr  = (const float*)d_in[8];
    const float* tdec = (const float*)d_in[9];
    const float* tfir = (const float*)d_in[10];
    const float* Wk   = (const float*)d_in[11];
    const float* Wv   = (const float*)d_in[12];
    const float* Wr   = (const float*)d_in[13];
    const float* Wo   = (const float*)d_in[14];
    float* out = (float*)d_out;

    cudaFuncSetAttribute(gemm_mma_kernel,
                         cudaFuncAttributeMaxDynamicSharedMemorySize, GEMM_SMEM);

    dim3 wgrid(C_ * C_ / 256, 3);
    conv_w_kernel<<<wgrid, 256>>>(Wk, Wv, Wr);

    embed_mix_kernel<<<BTC / 2 / 256, 256>>>(tok, xx, emb, tmk, tmv, tmr);

    dim3 ggrid(C_ / BN, M_ / BM, 3);   // (4, 128, 3)
    gemm_mma_kernel<<<ggrid, 256, GEMM_SMEM>>>();

    wkv_passA<<<(NCH * BC_) / 256, 256>>>(tdec);
    wkv_passB<<<BC_ / 256, 256>>>(aa, bb, pp, tdec);
    wkv_passC<<<(NCH * BC_) / 256, 256>>>(tdec, tfir);
    wkv_reduce<<<BC_ / 256, 256>>>();

    final_proj_kernel<<<(BC_ * 32) / 256, 256>>>(Wo, out);
}

// round 9
// speedup vs baseline: 6.1225x; 1.2126x over previous
#include <cuda_runtime.h>
#include <cuda_fp16.h>
#include <cstdint>
#include <cmath>

// Problem constants
#define B_   8
#define T_   2048
#define C_   1024
#define M_   (B_*T_)       // 16384
#define BTC  (B_*T_*C_)    // 16777216
#define BC_  (B_*C_)       // 8192

// Chunked scan
#define NCH 16
#define CL  (T_/NCH)       // 128

// ---------------------------------------------------------------------------
// Scratch (__device__ globals; no cudaMalloc allowed)
// ---------------------------------------------------------------------------
__device__ __half g_xk[BTC];
__device__ __half g_xv[BTC];
__device__ __half g_xr[BTC];
__device__ __half g_W16[3][C_*C_];
__device__ float g_k[BTC], g_v[BTC], g_r[BTC];
// scan scratch
__device__ float g_chA[NCH][BC_], g_chB[NCH][BC_], g_chP[NCH][BC_];
__device__ float g_inA[NCH][BC_], g_inB[NCH][BC_], g_inP[NCH][BC_];
__device__ float g_psum[NCH][BC_];
__device__ float g_ylast[BC_];
__device__ float g_z[BC_];

// ---------------------------------------------------------------------------
// Generic-PTX helpers (sm_80-class; safe for the harness's compute_103 build)
// ---------------------------------------------------------------------------
__device__ __forceinline__ uint32_t smem_u32(const void* p) {
    uint32_t a;
    asm("{ .reg .u64 t; cvta.to.shared.u64 t, %1; cvt.u32.u64 %0, t; }" : "=r"(a) : "l"(p));
    return a;
}
__device__ __forceinline__ void cpa16(uint32_t dst, const void* src) {
    asm volatile("cp.async.cg.shared.global [%0], [%1], 16;\n" :: "r"(dst), "l"(src));
}
__device__ __forceinline__ void cpa_commit() {
    asm volatile("cp.async.commit_group;\n" ::: "memory");
}
__device__ __forceinline__ void cpa_wait1() {
    asm volatile("cp.async.wait_group 1;\n" ::: "memory");
}
__device__ __forceinline__ void cpa_wait0() {
    asm volatile("cp.async.wait_group 0;\n" ::: "memory");
}
__device__ __forceinline__ void ldsm_x4(uint32_t& r0, uint32_t& r1, uint32_t& r2, uint32_t& r3,
                                        uint32_t addr) {
    asm volatile("ldmatrix.sync.aligned.m8n8.x4.shared.b16 {%0,%1,%2,%3}, [%4];"
                 : "=r"(r0), "=r"(r1), "=r"(r2), "=r"(r3) : "r"(addr));
}
__device__ __forceinline__ void mma16816(float& d0, float& d1, float& d2, float& d3,
                                         uint32_t a0, uint32_t a1, uint32_t a2, uint32_t a3,
                                         uint32_t b0, uint32_t b1) {
    asm volatile(
        "mma.sync.aligned.m16n8k16.row.col.f32.f16.f16.f32 "
        "{%0,%1,%2,%3}, {%4,%5,%6,%7}, {%8,%9}, {%0,%1,%2,%3};"
        : "+f"(d0), "+f"(d1), "+f"(d2), "+f"(d3)
        : "r"(a0), "r"(a1), "r"(a2), "r"(a3), "r"(b0), "r"(b1));
}

// ---------------------------------------------------------------------------
// K0: weights fp32 -> fp16
// ---------------------------------------------------------------------------
__global__ __launch_bounds__(256)
void conv_w_kernel(const float* __restrict__ Wk,
                   const float* __restrict__ Wv,
                   const float* __restrict__ Wr)
{
    int which = blockIdx.y;
    int i = blockIdx.x * 256 + threadIdx.x;
    const float* src = (which == 0) ? Wk : (which == 1) ? Wv : Wr;
    g_W16[which][i] = __float2half_rn(src[i]);
}

// ---------------------------------------------------------------------------
// K1: embedding gather + time-mix -> fp16 xk, xv, xr (half2 stores)
// ---------------------------------------------------------------------------
__global__ __launch_bounds__(256)
void embed_mix_kernel(const int*   __restrict__ tok,
                      const float* __restrict__ xx_init,
                      const float* __restrict__ emb,
                      const float* __restrict__ tmk,
                      const float* __restrict__ tmv,
                      const float* __restrict__ tmr)
{
    int idx2 = blockIdx.x * blockDim.x + threadIdx.x;   // < BTC/2
    int c2 = idx2 & 511;
    int bt = idx2 >> 9;
    int t  = bt & (T_ - 1);
    int b  = bt >> 11;
    int c  = c2 * 2;

    int token = tok[bt];
    float2 xc = *(const float2*)&emb[token * C_ + c];
    float2 xp;
    if (t == 0) xp = *(const float2*)&xx_init[b * C_ + c];
    else        xp = *(const float2*)&emb[tok[bt - 1] * C_ + c];

    float2 mk = *(const float2*)&tmk[c];
    float2 mv = *(const float2*)&tmv[c];
    float2 mr = *(const float2*)&tmr[c];

#define MIX_STORE(arr, m)  do {                                             \
        float v0 = xc.x * (m).x + xp.x * (1.0f - (m).x);                    \
        float v1 = xc.y * (m).y + xp.y * (1.0f - (m).y);                    \
        reinterpret_cast<__half2*>(arr)[idx2] =                             \
            __halves2half2(__float2half_rn(v0), __float2half_rn(v1));       \
    } while (0)

    MIX_STORE(g_xk, mk);
    MIX_STORE(g_xv, mv);
    MIX_STORE(g_xr, mr);
#undef MIX_STORE
}

// ---------------------------------------------------------------------------
// K2: fp16 NT GEMM: C[M,N] = A[M,K] * W[N,K]^T  (fp32 accumulate).
// Tiles: 128x128x32, 8 warps (warp tile 64x32), 3-stage cp.async pipeline,
// 2 CTAs/SM (occ=2 hides load/barrier overhead under the other CTA's MMAs).
// SMEM rows padded to 80B => conflict-free ldmatrix.
// blockIdx.z: 0 -> k, 1 -> v, 2 -> sigmoid -> r
// ---------------------------------------------------------------------------
#define BM 128
#define BN 128
#define BK 32
#define ROWB 80
#define AT_BYTES (BM * ROWB)             // 10240 A tile
#define BT_BYTES (BN * ROWB)             // 10240 W tile
#define STAGEB (AT_BYTES + BT_BYTES)     // 20480
#define NSTAGE 3
#define GEMM_SMEM (NSTAGE * STAGEB)      // 61440 (x2 CTAs = 122880 <= 227KB)
#define NKT (C_ / BK)                    // 32 K-chunks

__global__ __launch_bounds__(256, 2)
void gemm_mma_kernel()
{
    extern __shared__ char smem[];
    const uint32_t sb = smem_u32(smem);
    const int tid  = threadIdx.x;
    const int wid  = tid >> 5;
    const int lane = tid & 31;

    const int which = blockIdx.z;
    const int n0 = blockIdx.x * BN;
    const int m0 = blockIdx.y * BM;

    const __half* Ap = (which == 0) ? g_xk : (which == 1) ? g_xv : g_xr;
    const __half* Wp = g_W16[which];
    float* __restrict__ Cout = (which == 0) ? g_k : (which == 1) ? g_v : g_r;

    const char* A_g = (const char*)(Ap + (size_t)m0 * C_);
    const char* W_g = (const char*)(Wp + (size_t)n0 * C_);

    const int warp_m = (wid & 1) * 64;   // 2 warps along M
    const int warp_n = (wid >> 1) * 32;  // 4 warps along N

    float acc[4][4][4];
#pragma unroll
    for (int i = 0; i < 4; i++)
#pragma unroll
        for (int j = 0; j < 4; j++)
#pragma unroll
            for (int q = 0; q < 4; q++) acc[i][j][q] = 0.0f;

    // Load one K-chunk: A (128 rows x 64B), W (128 rows x 64B)
    auto issue_stage = [&](int kt, int stg) {
        const int kb = kt * BK * 2;              // byte offset along K
        uint32_t base = sb + stg * STAGEB;
        for (int g = tid; g < 512; g += 256) {   // A: 128 rows x 4 granules
            int r = g >> 2;
            int c = g & 3;
            cpa16(base + r * ROWB + c * 16, A_g + (size_t)r * (C_ * 2) + kb + c * 16);
        }
        for (int g = tid; g < 512; g += 256) {   // W: 128 rows x 4 granules
            int r = g >> 2;
            int c = g & 3;
            cpa16(base + AT_BYTES + r * ROWB + c * 16,
                  W_g + (size_t)r * (C_ * 2) + kb + c * 16);
        }
        cpa_commit();
    };

    issue_stage(0, 0);
    issue_stage(1, 1);

    const int l15 = lane & 15;
    const int l7  = lane & 7;
    const int b_rowadd = ((lane >> 4) & 1) * 8 + l7;
    const int b_koff   = ((lane >> 3) & 1) * 16;

    for (int kt = 0; kt < NKT; kt++) {
        if (kt == NKT - 1) cpa_wait0(); else cpa_wait1();
        __syncthreads();
        if (kt + 2 < NKT) issue_stage(kt + 2, (kt + 2) % NSTAGE);

        const uint32_t base = sb + (kt % NSTAGE) * STAGEB;
        const uint32_t ah = base;
        const uint32_t bw = base + AT_BYTES;

#pragma unroll
        for (int ks = 0; ks < 2; ks++) {
            uint32_t af[4][4];
            uint32_t bf[4][2];
            const uint32_t arow = (warp_m + l15) * ROWB + ks * 32 + (lane >> 4) * 16;
#pragma unroll
            for (int mt = 0; mt < 4; mt++)
                ldsm_x4(af[mt][0], af[mt][1], af[mt][2], af[mt][3],
                        ah + arow + mt * (16 * ROWB));
#pragma unroll
            for (int p = 0; p < 2; p++) {
                uint32_t addr = bw + (warp_n + p * 16 + b_rowadd) * ROWB + ks * 32 + b_koff;
                ldsm_x4(bf[2*p][0], bf[2*p][1], bf[2*p+1][0], bf[2*p+1][1], addr);
            }
#pragma unroll
            for (int mt = 0; mt < 4; mt++)
#pragma unroll
                for (int nt = 0; nt < 4; nt++)
                    mma16816(acc[mt][nt][0], acc[mt][nt][1], acc[mt][nt][2], acc[mt][nt][3],
                             af[mt][0], af[mt][1], af[mt][2], af[mt][3],
                             bf[nt][0], bf[nt][1]);
        }
    }

    // ---- epilogue: direct register -> global stores
    const int rbase = m0 + warp_m + (lane >> 2);
    const int cbase = n0 + warp_n + (lane & 3) * 2;
#pragma unroll
    for (int mt = 0; mt < 4; mt++) {
#pragma unroll
        for (int nt = 0; nt < 4; nt++) {
            float v0 = acc[mt][nt][0], v1 = acc[mt][nt][1];
            float v2 = acc[mt][nt][2], v3 = acc[mt][nt][3];
            if (which == 2) {
                v0 = 1.0f / (1.0f + __expf(-v0));
                v1 = 1.0f / (1.0f + __expf(-v1));
                v2 = 1.0f / (1.0f + __expf(-v2));
                v3 = 1.0f / (1.0f + __expf(-v3));
            }
            size_t r0 = (size_t)(rbase + mt * 16) * C_ + cbase + nt * 8;
            size_t r1 = r0 + 8 * C_;
            *(float2*)&Cout[r0] = make_float2(v0, v1);
            *(float2*)&Cout[r1] = make_float2(v2, v3);
        }
    }
}

// ---------------------------------------------------------------------------
// K3a: chunk-local WKV state summaries (A, B, P) — 16 chunks x 8192 channels.
// ---------------------------------------------------------------------------
__global__ __launch_bounds__(256)
void wkv_passA(const float* __restrict__ time_decay)
{
    const int tid = blockIdx.x * blockDim.x + threadIdx.x;  // 0..131071
    const int bc = tid & (BC_ - 1);
    const int j  = tid >> 13;
    const int c  = bc & (C_ - 1);
    const int b  = bc >> 10;

    const float w = -expf(time_decay[c]);
    float aa = 0.0f, bb = 0.0f, pp = -1e30f;

    const int base = (b * T_ + j * CL) * C_ + c;
#pragma unroll 4
    for (int i = 0; i < CL; i++) {
        float kt = g_k[base + i * C_];
        float vt = g_v[base + i * C_];
        float ww2 = pp + w;
        float d2  = ww2 - kt;
        float es  = __expf(-fabsf(d2));
        float e1  = (d2 >= 0.0f) ? 1.0f : es;
        float e2  = (d2 >= 0.0f) ? es : 1.0f;
        aa = e1 * aa + e2 * vt;
        bb = e1 * bb + e2;
        pp = fmaxf(ww2, kt);
    }
    g_chA[j][bc] = aa;
    g_chB[j][bc] = bb;
    g_chP[j][bc] = pp;
}

// ---------------------------------------------------------------------------
// K3b: serial compose over 16 chunk summaries -> incoming state per chunk.
// ---------------------------------------------------------------------------
__global__ __launch_bounds__(256)
void wkv_passB(const float* __restrict__ aa_init,
               const float* __restrict__ bb_init,
               const float* __restrict__ pp_init,
               const float* __restrict__ time_decay)
{
    const int bc = blockIdx.x * blockDim.x + threadIdx.x;  // 0..8191
    const int c  = bc & (C_ - 1);

    float aa = aa_init[bc], bb = bb_init[bc], pp = pp_init[bc];
    const float Lw = (float)CL * (-expf(time_decay[c]));

#pragma unroll
    for (int j = 0; j < NCH; j++) {
        g_inA[j][bc] = aa;
        g_inB[j][bc] = bb;
        g_inP[j][bc] = pp;
        float q  = pp + Lw;
        float Pj = g_chP[j][bc];
        float Aj = g_chA[j][bc];
        float Bj = g_chB[j][bc];
        float Pn = fmaxf(q, Pj);
        float e1 = __expf(q - Pn);
        float e2 = __expf(Pj - Pn);
        aa = e1 * aa + e2 * Aj;
        bb = e1 * bb + e2 * Bj;
        pp = Pn;
    }
}

// ---------------------------------------------------------------------------
// K3c: replay each chunk with its incoming state; emit partial ysum + ylast.
// ---------------------------------------------------------------------------
__global__ __launch_bounds__(256)
void wkv_passC(const float* __restrict__ time_decay,
               const float* __restrict__ time_first)
{
    const int tid = blockIdx.x * blockDim.x + threadIdx.x;  // 0..131071
    const int bc = tid & (BC_ - 1);
    const int j  = tid >> 13;
    const int c  = bc & (C_ - 1);
    const int b  = bc >> 10;

    const float w = -expf(time_decay[c]);
    const float u = time_first[c];

    float aa = g_inA[j][bc];
    float bb = g_inB[j][bc];
    float pp = g_inP[j][bc];

    float ysum = 0.0f;
    float y = 0.0f;

    const int base = (b * T_ + j * CL) * C_ + c;
#pragma unroll 4
    for (int i = 0; i < CL; i++) {
        float kt = g_k[base + i * C_];
        float vt = g_v[base + i * C_];
        float rt = g_r[base + i * C_];
        float ww = u + kt;
        float d  = pp - ww;
        float es = __expf(-fabsf(d));
        float e1 = (d >= 0.0f) ? 1.0f : es;
        float e2 = (d >= 0.0f) ? es : 1.0f;
        y = rt * __fdividef(e1 * aa + e2 * vt, e1 * bb + e2);
        ysum += y;
        float ww2 = pp + w;
        float d2  = ww2 - kt;
        float es2 = __expf(-fabsf(d2));
        float e1b = (d2 >= 0.0f) ? 1.0f : es2;
        float e2b = (d2 >= 0.0f) ? es2 : 1.0f;
        aa = e1b * aa + e2b * vt;
        bb = e1b * bb + e2b;
        pp = fmaxf(ww2, kt);
    }
    g_psum[j][bc] = ysum;
    if (j == NCH - 1) g_ylast[bc] = y;
}

// ---------------------------------------------------------------------------
// K3d: reduce partials -> z = 0.5*(ylast + mean)
// ---------------------------------------------------------------------------
__global__ __launch_bounds__(256)
void wkv_reduce()
{
    const int bc = blockIdx.x * blockDim.x + threadIdx.x;  // 0..8191
    float s = 0.0f;
#pragma unroll
    for (int j = 0; j < NCH; j++) s += g_psum[j][bc];
    g_z[bc] = 0.5f * (g_ylast[bc] + s * (1.0f / (float)T_));
}

// ---------------------------------------------------------------------------
// K4: tiny output GEMM hx[b,d] = sum_c z[b,c] * Wo[d,c]; out = stack([hx,hx])
// ---------------------------------------------------------------------------
__global__ __launch_bounds__(256)
void final_proj_kernel(const float* __restrict__ Wo,
                       float* __restrict__ out)
{
    int gw   = (blockIdx.x * blockDim.x + threadIdx.x) >> 5;
    int lane = threadIdx.x & 31;
    if (gw >= BC_) return;
    int b = gw >> 10;
    int d = gw & (C_ - 1);

    const float* z  = g_z + b * C_;
    const float* wr = Wo + (size_t)d * C_;
    float s = 0.0f;
#pragma unroll 8
    for (int c = lane; c < C_; c += 32)
        s = fmaf(z[c], wr[c], s);
#pragma unroll
    for (int o = 16; o > 0; o >>= 1)
        s += __shfl_xor_sync(0xFFFFFFFFu, s, o);
    if (lane == 0) {
        out[b * C_ + d]       = s;
        out[BC_ + b * C_ + d] = s;
    }
}

// ---------------------------------------------------------------------------
extern "C" void kernel_launch(void* const* d_in, const int* in_sizes, int n_in,
                              void* d_out, int out_size)
{
    const int*   tok  = (const int*)  d_in[0];
    const float* xx   = (const float*)d_in[1];
    const float* aa   = (const float*)d_in[2];
    const float* bb   = (const float*)d_in[3];
    const float* pp   = (const float*)d_in[4];
    const float* emb  = (const float*)d_in[5];
    const float* tmk  = (const float*)d_in[6];
    const float* tmv  = (const float*)d_in[7];
    const float* tmr  = (const float*)d_in[8];
    const float* tdec = (const float*)d_in[9];
    const float* tfir = (const float*)d_in[10];
    const float* Wk   = (const float*)d_in[11];
    const float* Wv   = (const float*)d_in[12];
    const float* Wr   = (const float*)d_in[13];
    const float* Wo   = (const float*)d_in[14];
    float* out = (float*)d_out;

    cudaFuncSetAttribute(gemm_mma_kernel,
                         cudaFuncAttributeMaxDynamicSharedMemorySize, GEMM_SMEM);

    dim3 wgrid(C_ * C_ / 256, 3);
    conv_w_kernel<<<wgrid, 256>>>(Wk, Wv, Wr);

    embed_mix_kernel<<<BTC / 2 / 256, 256>>>(tok, xx, emb, tmk, tmv, tmr);

    dim3 ggrid(C_ / BN, M_ / BM, 3);   // (8, 128, 3)
    gemm_mma_kernel<<<ggrid, 256, GEMM_SMEM>>>();

    wkv_passA<<<(NCH * BC_) / 256, 256>>>(tdec);
    wkv_passB<<<BC_ / 256, 256>>>(aa, bb, pp, tdec);
    wkv_passC<<<(NCH * BC_) / 256, 256>>>(tdec, tfir);
    wkv_reduce<<<BC_ / 256, 256>>>();

    final_proj_kernel<<<(BC_ * 32) / 256, 256>>>(Wo, out);
}

// round 10
// speedup vs baseline: 6.6462x; 1.0855x over previous
#include <cuda_runtime.h>
#include <cuda_fp16.h>
#include <cstdint>
#include <cmath>

// Problem constants
#define B_   8
#define T_   2048
#define C_   1024
#define M_   (B_*T_)       // 16384
#define BTC  (B_*T_*C_)    // 16777216
#define BC_  (B_*C_)       // 8192

// Chunked scan
#define NCH 16
#define CL  (T_/NCH)       // 128

// ---------------------------------------------------------------------------
// Scratch (__device__ globals; no cudaMalloc allowed)
// ---------------------------------------------------------------------------
__device__ __half g_xk[BTC];
__device__ __half g_xv[BTC];
__device__ __half g_xr[BTC];
__device__ __half g_W16[3][C_*C_];
__device__ __half g_k16[BTC], g_v16[BTC], g_r16[BTC];
// scan scratch
__device__ float g_chA[NCH][BC_], g_chB[NCH][BC_], g_chP[NCH][BC_];
__device__ float g_inA[NCH][BC_], g_inB[NCH][BC_], g_inP[NCH][BC_];
__device__ float g_psum[NCH][BC_];
__device__ float g_ylast[BC_];
__device__ float g_z[BC_];

// ---------------------------------------------------------------------------
// Generic-PTX helpers (sm_80-class; safe for the harness's compute_103 build)
// ---------------------------------------------------------------------------
__device__ __forceinline__ uint32_t smem_u32(const void* p) {
    uint32_t a;
    asm("{ .reg .u64 t; cvta.to.shared.u64 t, %1; cvt.u32.u64 %0, t; }" : "=r"(a) : "l"(p));
    return a;
}
__device__ __forceinline__ void cpa16(uint32_t dst, const void* src) {
    asm volatile("cp.async.cg.shared.global [%0], [%1], 16;\n" :: "r"(dst), "l"(src));
}
__device__ __forceinline__ void cpa_commit() {
    asm volatile("cp.async.commit_group;\n" ::: "memory");
}
__device__ __forceinline__ void cpa_wait1() {
    asm volatile("cp.async.wait_group 1;\n" ::: "memory");
}
__device__ __forceinline__ void cpa_wait0() {
    asm volatile("cp.async.wait_group 0;\n" ::: "memory");
}
__device__ __forceinline__ void ldsm_x4(uint32_t& r0, uint32_t& r1, uint32_t& r2, uint32_t& r3,
                                        uint32_t addr) {
    asm volatile("ldmatrix.sync.aligned.m8n8.x4.shared.b16 {%0,%1,%2,%3}, [%4];"
                 : "=r"(r0), "=r"(r1), "=r"(r2), "=r"(r3) : "r"(addr));
}
__device__ __forceinline__ void mma16816(float& d0, float& d1, float& d2, float& d3,
                                         uint32_t a0, uint32_t a1, uint32_t a2, uint32_t a3,
                                         uint32_t b0, uint32_t b1) {
    asm volatile(
        "mma.sync.aligned.m16n8k16.row.col.f32.f16.f16.f32 "
        "{%0,%1,%2,%3}, {%4,%5,%6,%7}, {%8,%9}, {%0,%1,%2,%3};"
        : "+f"(d0), "+f"(d1), "+f"(d2), "+f"(d3)
        : "r"(a0), "r"(a1), "r"(a2), "r"(a3), "r"(b0), "r"(b1));
}

// ---------------------------------------------------------------------------
// K0: weights fp32 -> fp16
// ---------------------------------------------------------------------------
__global__ __launch_bounds__(256)
void conv_w_kernel(const float* __restrict__ Wk,
                   const float* __restrict__ Wv,
                   const float* __restrict__ Wr)
{
    int which = blockIdx.y;
    int i = blockIdx.x * 256 + threadIdx.x;
    const float* src = (which == 0) ? Wk : (which == 1) ? Wv : Wr;
    g_W16[which][i] = __float2half_rn(src[i]);
}

// ---------------------------------------------------------------------------
// K1: embedding gather + time-mix -> fp16 xk, xv, xr (half2 stores)
// ---------------------------------------------------------------------------
__global__ __launch_bounds__(256)
void embed_mix_kernel(const int*   __restrict__ tok,
                      const float* __restrict__ xx_init,
                      const float* __restrict__ emb,
                      const float* __restrict__ tmk,
                      const float* __restrict__ tmv,
                      const float* __restrict__ tmr)
{
    int idx2 = blockIdx.x * blockDim.x + threadIdx.x;   // < BTC/2
    int c2 = idx2 & 511;
    int bt = idx2 >> 9;
    int t  = bt & (T_ - 1);
    int b  = bt >> 11;
    int c  = c2 * 2;

    int token = tok[bt];
    float2 xc = *(const float2*)&emb[token * C_ + c];
    float2 xp;
    if (t == 0) xp = *(const float2*)&xx_init[b * C_ + c];
    else        xp = *(const float2*)&emb[tok[bt - 1] * C_ + c];

    float2 mk = *(const float2*)&tmk[c];
    float2 mv = *(const float2*)&tmv[c];
    float2 mr = *(const float2*)&tmr[c];

#define MIX_STORE(arr, m)  do {                                             \
        float v0 = xc.x * (m).x + xp.x * (1.0f - (m).x);                    \
        float v1 = xc.y * (m).y + xp.y * (1.0f - (m).y);                    \
        reinterpret_cast<__half2*>(arr)[idx2] =                             \
            __halves2half2(__float2half_rn(v0), __float2half_rn(v1));       \
    } while (0)

    MIX_STORE(g_xk, mk);
    MIX_STORE(g_xv, mv);
    MIX_STORE(g_xr, mr);
#undef MIX_STORE
}

// ---------------------------------------------------------------------------
// K2: fp16 NT GEMM: C[M,N] = A[M,K] * W[N,K]^T  (fp32 accumulate, fp16 out).
// Tiles: 128x128x64, 8 warps (warp tile 64x32), 3-stage cp.async pipeline,
// 2 CTAs/SM. SMEM rows = 128B data + 16B pad (144B) => conflict-free ldmatrix.
// blockIdx.z: 0 -> k, 1 -> v, 2 -> sigmoid -> r
// ---------------------------------------------------------------------------
#define BM 128
#define BN 128
#define BK 64
#define ROWB 144                          // 128 data + 16 pad
#define AT_BYTES (BM * ROWB)              // 18432
#define BT_BYTES (BN * ROWB)              // 18432
#define STAGEB (AT_BYTES + BT_BYTES)      // 36864
#define NSTAGE 3
#define GEMM_SMEM (NSTAGE * STAGEB)       // 110592 (x2 CTAs = 221184)
#define NKT (C_ / BK)                     // 16 K-chunks

__global__ __launch_bounds__(256, 2)
void gemm_mma_kernel()
{
    extern __shared__ char smem[];
    const uint32_t sb = smem_u32(smem);
    const int tid  = threadIdx.x;
    const int wid  = tid >> 5;
    const int lane = tid & 31;

    const int which = blockIdx.z;
    const int n0 = blockIdx.x * BN;
    const int m0 = blockIdx.y * BM;

    const __half* Ap = (which == 0) ? g_xk : (which == 1) ? g_xv : g_xr;
    const __half* Wp = g_W16[which];
    __half* __restrict__ Cout = (which == 0) ? g_k16 : (which == 1) ? g_v16 : g_r16;

    const char* A_g = (const char*)(Ap + (size_t)m0 * C_);
    const char* W_g = (const char*)(Wp + (size_t)n0 * C_);

    const int warp_m = (wid & 1) * 64;   // 2 warps along M
    const int warp_n = (wid >> 1) * 32;  // 4 warps along N

    float acc[4][4][4];
#pragma unroll
    for (int i = 0; i < 4; i++)
#pragma unroll
        for (int j = 0; j < 4; j++)
#pragma unroll
            for (int q = 0; q < 4; q++) acc[i][j][q] = 0.0f;

    // Load one K-chunk: A (128 rows x 128B), W (128 rows x 128B)
    auto issue_stage = [&](int kt, int stg) {
        const int kb = kt * BK * 2;              // byte offset along K (128B)
        uint32_t base = sb + stg * STAGEB;
        for (int g = tid; g < 1024; g += 256) {  // A: 128 rows x 8 granules
            int r = g >> 3;
            int c = g & 7;
            cpa16(base + r * ROWB + c * 16, A_g + (size_t)r * (C_ * 2) + kb + c * 16);
        }
        for (int g = tid; g < 1024; g += 256) {  // W: 128 rows x 8 granules
            int r = g >> 3;
            int c = g & 7;
            cpa16(base + AT_BYTES + r * ROWB + c * 16,
                  W_g + (size_t)r * (C_ * 2) + kb + c * 16);
        }
        cpa_commit();
    };

    issue_stage(0, 0);
    issue_stage(1, 1);

    const int l15 = lane & 15;
    const int l7  = lane & 7;
    const int b_rowadd = ((lane >> 4) & 1) * 8 + l7;
    const int b_koff   = ((lane >> 3) & 1) * 16;

    for (int kt = 0; kt < NKT; kt++) {
        if (kt == NKT - 1) cpa_wait0(); else cpa_wait1();
        __syncthreads();
        if (kt + 2 < NKT) issue_stage(kt + 2, (kt + 2) % NSTAGE);

        const uint32_t base = sb + (kt % NSTAGE) * STAGEB;
        const uint32_t ah = base;
        const uint32_t bw = base + AT_BYTES;

#pragma unroll
        for (int ks = 0; ks < 4; ks++) {          // 4 x K16 within 64-chunk
            uint32_t af[4][4];
            uint32_t bf[4][2];
            const uint32_t arow = (warp_m + l15) * ROWB + ks * 32 + (lane >> 4) * 16;
#pragma unroll
            for (int mt = 0; mt < 4; mt++)
                ldsm_x4(af[mt][0], af[mt][1], af[mt][2], af[mt][3],
                        ah + arow + mt * (16 * ROWB));
#pragma unroll
            for (int p = 0; p < 2; p++) {
                uint32_t addr = bw + (warp_n + p * 16 + b_rowadd) * ROWB + ks * 32 + b_koff;
                ldsm_x4(bf[2*p][0], bf[2*p][1], bf[2*p+1][0], bf[2*p+1][1], addr);
            }
#pragma unroll
            for (int mt = 0; mt < 4; mt++)
#pragma unroll
                for (int nt = 0; nt < 4; nt++)
                    mma16816(acc[mt][nt][0], acc[mt][nt][1], acc[mt][nt][2], acc[mt][nt][3],
                             af[mt][0], af[mt][1], af[mt][2], af[mt][3],
                             bf[nt][0], bf[nt][1]);
        }
    }

    // ---- epilogue: fp16 half2 stores direct to global
    const int rbase = m0 + warp_m + (lane >> 2);
    const int cbase = n0 + warp_n + (lane & 3) * 2;
#pragma unroll
    for (int mt = 0; mt < 4; mt++) {
#pragma unroll
        for (int nt = 0; nt < 4; nt++) {
            float v0 = acc[mt][nt][0], v1 = acc[mt][nt][1];
            float v2 = acc[mt][nt][2], v3 = acc[mt][nt][3];
            if (which == 2) {
                v0 = 1.0f / (1.0f + __expf(-v0));
                v1 = 1.0f / (1.0f + __expf(-v1));
                v2 = 1.0f / (1.0f + __expf(-v2));
                v3 = 1.0f / (1.0f + __expf(-v3));
            }
            size_t r0 = (size_t)(rbase + mt * 16) * C_ + cbase + nt * 8;
            size_t r1 = r0 + 8 * C_;
            *reinterpret_cast<__half2*>(&Cout[r0]) =
                __halves2half2(__float2half_rn(v0), __float2half_rn(v1));
            *reinterpret_cast<__half2*>(&Cout[r1]) =
                __halves2half2(__float2half_rn(v2), __float2half_rn(v3));
        }
    }
}

// ---------------------------------------------------------------------------
// K3a: chunk-local WKV state summaries (A, B, P) — 16 chunks x 8192 channels.
// ---------------------------------------------------------------------------
__global__ __launch_bounds__(256)
void wkv_passA(const float* __restrict__ time_decay)
{
    const int tid = blockIdx.x * blockDim.x + threadIdx.x;  // 0..131071
    const int bc = tid & (BC_ - 1);
    const int j  = tid >> 13;
    const int c  = bc & (C_ - 1);
    const int b  = bc >> 10;

    const float w = -expf(time_decay[c]);
    float aa = 0.0f, bb = 0.0f, pp = -1e30f;

    const int base = (b * T_ + j * CL) * C_ + c;
#pragma unroll 4
    for (int i = 0; i < CL; i++) {
        float kt = __half2float(g_k16[base + i * C_]);
        float vt = __half2float(g_v16[base + i * C_]);
        float ww2 = pp + w;
        float d2  = ww2 - kt;
        float es  = __expf(-fabsf(d2));
        float e1  = (d2 >= 0.0f) ? 1.0f : es;
        float e2  = (d2 >= 0.0f) ? es : 1.0f;
        aa = e1 * aa + e2 * vt;
        bb = e1 * bb + e2;
        pp = fmaxf(ww2, kt);
    }
    g_chA[j][bc] = aa;
    g_chB[j][bc] = bb;
    g_chP[j][bc] = pp;
}

// ---------------------------------------------------------------------------
// K3b: serial compose over 16 chunk summaries -> incoming state per chunk.
// ---------------------------------------------------------------------------
__global__ __launch_bounds__(256)
void wkv_passB(const float* __restrict__ aa_init,
               const float* __restrict__ bb_init,
               const float* __restrict__ pp_init,
               const float* __restrict__ time_decay)
{
    const int bc = blockIdx.x * blockDim.x + threadIdx.x;  // 0..8191
    const int c  = bc & (C_ - 1);

    float aa = aa_init[bc], bb = bb_init[bc], pp = pp_init[bc];
    const float Lw = (float)CL * (-expf(time_decay[c]));

#pragma unroll
    for (int j = 0; j < NCH; j++) {
        g_inA[j][bc] = aa;
        g_inB[j][bc] = bb;
        g_inP[j][bc] = pp;
        float q  = pp + Lw;
        float Pj = g_chP[j][bc];
        float Aj = g_chA[j][bc];
        float Bj = g_chB[j][bc];
        float Pn = fmaxf(q, Pj);
        float e1 = __expf(q - Pn);
        float e2 = __expf(Pj - Pn);
        aa = e1 * aa + e2 * Aj;
        bb = e1 * bb + e2 * Bj;
        pp = Pn;
    }
}

// ---------------------------------------------------------------------------
// K3c: replay each chunk with its incoming state; emit partial ysum + ylast.
// ---------------------------------------------------------------------------
__global__ __launch_bounds__(256)
void wkv_passC(const float* __restrict__ time_decay,
               const float* __restrict__ time_first)
{
    const int tid = blockIdx.x * blockDim.x + threadIdx.x;  // 0..131071
    const int bc = tid & (BC_ - 1);
    const int j  = tid >> 13;
    const int c  = bc & (C_ - 1);
    const int b  = bc >> 10;

    const float w = -expf(time_decay[c]);
    const float u = time_first[c];

    float aa = g_inA[j][bc];
    float bb = g_inB[j][bc];
    float pp = g_inP[j][bc];

    float ysum = 0.0f;
    float y = 0.0f;

    const int base = (b * T_ + j * CL) * C_ + c;
#pragma unroll 4
    for (int i = 0; i < CL; i++) {
        float kt = __half2float(g_k16[base + i * C_]);
        float vt = __half2float(g_v16[base + i * C_]);
        float rt = __half2float(g_r16[base + i * C_]);
        float ww = u + kt;
        float d  = pp - ww;
        float es = __expf(-fabsf(d));
        float e1 = (d >= 0.0f) ? 1.0f : es;
        float e2 = (d >= 0.0f) ? es : 1.0f;
        y = rt * __fdividef(e1 * aa + e2 * vt, e1 * bb + e2);
        ysum += y;
        float ww2 = pp + w;
        float d2  = ww2 - kt;
        float es2 = __expf(-fabsf(d2));
        float e1b = (d2 >= 0.0f) ? 1.0f : es2;
        float e2b = (d2 >= 0.0f) ? es2 : 1.0f;
        aa = e1b * aa + e2b * vt;
        bb = e1b * bb + e2b;
        pp = fmaxf(ww2, kt);
    }
    g_psum[j][bc] = ysum;
    if (j == NCH - 1) g_ylast[bc] = y;
}

// ---------------------------------------------------------------------------
// K3d: reduce partials -> z = 0.5*(ylast + mean)
// ---------------------------------------------------------------------------
__global__ __launch_bounds__(256)
void wkv_reduce()
{
    const int bc = blockIdx.x * blockDim.x + threadIdx.x;  // 0..8191
    float s = 0.0f;
#pragma unroll
    for (int j = 0; j < NCH; j++) s += g_psum[j][bc];
    g_z[bc] = 0.5f * (g_ylast[bc] + s * (1.0f / (float)T_));
}

// ---------------------------------------------------------------------------
// K4: tiny output GEMM hx[b,d] = sum_c z[b,c] * Wo[d,c]; out = stack([hx,hx])
// ---------------------------------------------------------------------------
__global__ __launch_bounds__(256)
void final_proj_kernel(const float* __restrict__ Wo,
                       float* __restrict__ out)
{
    int gw   = (blockIdx.x * blockDim.x + threadIdx.x) >> 5;
    int lane = threadIdx.x & 31;
    if (gw >= BC_) return;
    int b = gw >> 10;
    int d = gw & (C_ - 1);

    const float* z  = g_z + b * C_;
    const float* wr = Wo + (size_t)d * C_;
    float s = 0.0f;
#pragma unroll 8
    for (int c = lane; c < C_; c += 32)
        s = fmaf(z[c], wr[c], s);
#pragma unroll
    for (int o = 16; o > 0; o >>= 1)
        s += __shfl_xor_sync(0xFFFFFFFFu, s, o);
    if (lane == 0) {
        out[b * C_ + d]       = s;
        out[BC_ + b * C_ + d] = s;
    }
}

// ---------------------------------------------------------------------------
extern "C" void kernel_launch(void* const* d_in, const int* in_sizes, int n_in,
                              void* d_out, int out_size)
{
    const int*   tok  = (const int*)  d_in[0];
    const float* xx   = (const float*)d_in[1];
    const float* aa   = (const float*)d_in[2];
    const float* bb   = (const float*)d_in[3];
    const float* pp   = (const float*)d_in[4];
    const float* emb  = (const float*)d_in[5];
    const float* tmk  = (const float*)d_in[6];
    const float* tmv  = (const float*)d_in[7];
    const float* tmr  = (const float*)d_in[8];
    const float* tdec = (const float*)d_in[9];
    const float* tfir = (const float*)d_in[10];
    const float* Wk   = (const float*)d_in[11];
    const float* Wv   = (const float*)d_in[12];
    const float* Wr   = (const float*)d_in[13];
    const float* Wo   = (const float*)d_in[14];
    float* out = (float*)d_out;

    cudaFuncSetAttribute(gemm_mma_kernel,
                         cudaFuncAttributeMaxDynamicSharedMemorySize, GEMM_SMEM);

    dim3 wgrid(C_ * C_ / 256, 3);
    conv_w_kernel<<<wgrid, 256>>>(Wk, Wv, Wr);

    embed_mix_kernel<<<BTC / 2 / 256, 256>>>(tok, xx, emb, tmk, tmv, tmr);

    dim3 ggrid(C_ / BN, M_ / BM, 3);   // (8, 128, 3)
    gemm_mma_kernel<<<ggrid, 256, GEMM_SMEM>>>();

    wkv_passA<<<(NCH * BC_) / 256, 256>>>(tdec);
    wkv_passB<<<BC_ / 256, 256>>>(aa, bb, pp, tdec);
    wkv_passC<<<(NCH * BC_) / 256, 256>>>(tdec, tfir);
    wkv_reduce<<<BC_ / 256, 256>>>();

    final_proj_kernel<<<(BC_ * 32) / 256, 256>>>(Wo, out);
}

// round 11
// speedup vs baseline: 6.8951x; 1.0374x over previous
#include <cuda_runtime.h>
#include <cuda_fp16.h>
#include <cstdint>
#include <cmath>

// Problem constants
#define B_   8
#define T_   2048
#define C_   1024
#define M_   (B_*T_)       // 16384
#define BTC  (B_*T_*C_)    // 16777216
#define BC_  (B_*C_)       // 8192

// Chunked scan
#define NCH 32
#define CL  (T_/NCH)       // 64

// ---------------------------------------------------------------------------
// Scratch (__device__ globals; no cudaMalloc allowed)
// ---------------------------------------------------------------------------
__device__ __half g_xk[BTC];
__device__ __half g_xv[BTC];
__device__ __half g_xr[BTC];
__device__ __half g_W16[3][C_*C_];
__device__ __half g_k16[BTC], g_v16[BTC], g_r16[BTC];
// scan scratch
__device__ float g_chA[NCH][BC_], g_chB[NCH][BC_], g_chP[NCH][BC_];
__device__ float g_inA[NCH][BC_], g_inB[NCH][BC_], g_inP[NCH][BC_];
__device__ float g_psum[NCH][BC_];
__device__ float g_ylast[BC_];
__device__ float g_z[BC_];

// ---------------------------------------------------------------------------
// Generic-PTX helpers (sm_80-class; safe for the harness's compute_103 build)
// ---------------------------------------------------------------------------
__device__ __forceinline__ uint32_t smem_u32(const void* p) {
    uint32_t a;
    asm("{ .reg .u64 t; cvta.to.shared.u64 t, %1; cvt.u32.u64 %0, t; }" : "=r"(a) : "l"(p));
    return a;
}
__device__ __forceinline__ void cpa16(uint32_t dst, const void* src) {
    asm volatile("cp.async.cg.shared.global [%0], [%1], 16;\n" :: "r"(dst), "l"(src));
}
__device__ __forceinline__ void cpa_commit() {
    asm volatile("cp.async.commit_group;\n" ::: "memory");
}
__device__ __forceinline__ void cpa_wait1() {
    asm volatile("cp.async.wait_group 1;\n" ::: "memory");
}
__device__ __forceinline__ void cpa_wait0() {
    asm volatile("cp.async.wait_group 0;\n" ::: "memory");
}
__device__ __forceinline__ void ldsm_x4(uint32_t& r0, uint32_t& r1, uint32_t& r2, uint32_t& r3,
                                        uint32_t addr) {
    asm volatile("ldmatrix.sync.aligned.m8n8.x4.shared.b16 {%0,%1,%2,%3}, [%4];"
                 : "=r"(r0), "=r"(r1), "=r"(r2), "=r"(r3) : "r"(addr));
}
__device__ __forceinline__ void mma16816(float& d0, float& d1, float& d2, float& d3,
                                         uint32_t a0, uint32_t a1, uint32_t a2, uint32_t a3,
                                         uint32_t b0, uint32_t b1) {
    asm volatile(
        "mma.sync.aligned.m16n8k16.row.col.f32.f16.f16.f32 "
        "{%0,%1,%2,%3}, {%4,%5,%6,%7}, {%8,%9}, {%0,%1,%2,%3};"
        : "+f"(d0), "+f"(d1), "+f"(d2), "+f"(d3)
        : "r"(a0), "r"(a1), "r"(a2), "r"(a3), "r"(b0), "r"(b1));
}

// ---------------------------------------------------------------------------
// K0: weights fp32 -> fp16
// ---------------------------------------------------------------------------
__global__ __launch_bounds__(256)
void conv_w_kernel(const float* __restrict__ Wk,
                   const float* __restrict__ Wv,
                   const float* __restrict__ Wr)
{
    int which = blockIdx.y;
    int i = blockIdx.x * 256 + threadIdx.x;
    const float* src = (which == 0) ? Wk : (which == 1) ? Wv : Wr;
    g_W16[which][i] = __float2half_rn(src[i]);
}

// ---------------------------------------------------------------------------
// K1: embedding gather + time-mix -> fp16 xk, xv, xr (4 channels per thread)
// ---------------------------------------------------------------------------
__global__ __launch_bounds__(256)
void embed_mix_kernel(const int*   __restrict__ tok,
                      const float* __restrict__ xx_init,
                      const float* __restrict__ emb,
                      const float* __restrict__ tmk,
                      const float* __restrict__ tmv,
                      const float* __restrict__ tmr)
{
    int idx4 = blockIdx.x * blockDim.x + threadIdx.x;   // < BTC/4
    int c4 = idx4 & 255;
    int bt = idx4 >> 8;
    int t  = bt & (T_ - 1);
    int b  = bt >> 11;
    int c  = c4 * 4;

    int token = tok[bt];
    float4 xc = *(const float4*)&emb[token * C_ + c];
    float4 xp;
    if (t == 0) xp = *(const float4*)&xx_init[b * C_ + c];
    else        xp = *(const float4*)&emb[tok[bt - 1] * C_ + c];

    float4 mk = *(const float4*)&tmk[c];
    float4 mv = *(const float4*)&tmv[c];
    float4 mr = *(const float4*)&tmr[c];

#define MIX_STORE(arr, m)  do {                                             \
        float v0 = xc.x * (m).x + xp.x * (1.0f - (m).x);                    \
        float v1 = xc.y * (m).y + xp.y * (1.0f - (m).y);                    \
        float v2 = xc.z * (m).z + xp.z * (1.0f - (m).z);                    \
        float v3 = xc.w * (m).w + xp.w * (1.0f - (m).w);                    \
        __half2 h01 = __halves2half2(__float2half_rn(v0), __float2half_rn(v1)); \
        __half2 h23 = __halves2half2(__float2half_rn(v2), __float2half_rn(v3)); \
        *reinterpret_cast<uint2*>(&(arr)[(size_t)idx4 * 4]) =               \
            make_uint2(*(uint32_t*)&h01, *(uint32_t*)&h23);                 \
    } while (0)

    MIX_STORE(g_xk, mk);
    MIX_STORE(g_xv, mv);
    MIX_STORE(g_xr, mr);
#undef MIX_STORE
}

// ---------------------------------------------------------------------------
// K2: fp16 NT GEMM: C[M,N] = A[M,K] * W[N,K]^T  (fp32 accumulate, fp16 out).
// Tiles: 128x128x64, 8 warps (warp tile 64x32), 3-stage cp.async pipeline,
// 2 CTAs/SM. SMEM rows = 128B data + 16B pad (144B) => conflict-free ldmatrix.
// blockIdx.z: 0 -> k, 1 -> v, 2 -> sigmoid -> r
// ---------------------------------------------------------------------------
#define BM 128
#define BN 128
#define BK 64
#define ROWB 144                          // 128 data + 16 pad
#define AT_BYTES (BM * ROWB)              // 18432
#define BT_BYTES (BN * ROWB)              // 18432
#define STAGEB (AT_BYTES + BT_BYTES)      // 36864
#define NSTAGE 3
#define GEMM_SMEM (NSTAGE * STAGEB)       // 110592 (x2 CTAs = 221184)
#define NKT (C_ / BK)                     // 16 K-chunks

__global__ __launch_bounds__(256, 2)
void gemm_mma_kernel()
{
    extern __shared__ char smem[];
    const uint32_t sb = smem_u32(smem);
    const int tid  = threadIdx.x;
    const int wid  = tid >> 5;
    const int lane = tid & 31;

    const int which = blockIdx.z;
    const int n0 = blockIdx.x * BN;
    const int m0 = blockIdx.y * BM;

    const __half* Ap = (which == 0) ? g_xk : (which == 1) ? g_xv : g_xr;
    const __half* Wp = g_W16[which];
    __half* __restrict__ Cout = (which == 0) ? g_k16 : (which == 1) ? g_v16 : g_r16;

    const char* A_g = (const char*)(Ap + (size_t)m0 * C_);
    const char* W_g = (const char*)(Wp + (size_t)n0 * C_);

    const int warp_m = (wid & 1) * 64;   // 2 warps along M
    const int warp_n = (wid >> 1) * 32;  // 4 warps along N

    float acc[4][4][4];
#pragma unroll
    for (int i = 0; i < 4; i++)
#pragma unroll
        for (int j = 0; j < 4; j++)
#pragma unroll
            for (int q = 0; q < 4; q++) acc[i][j][q] = 0.0f;

    // Load one K-chunk: A (128 rows x 128B), W (128 rows x 128B)
    auto issue_stage = [&](int kt, int stg) {
        const int kb = kt * BK * 2;              // byte offset along K (128B)
        uint32_t base = sb + stg * STAGEB;
        for (int g = tid; g < 1024; g += 256) {  // A: 128 rows x 8 granules
            int r = g >> 3;
            int c = g & 7;
            cpa16(base + r * ROWB + c * 16, A_g + (size_t)r * (C_ * 2) + kb + c * 16);
        }
        for (int g = tid; g < 1024; g += 256) {  // W: 128 rows x 8 granules
            int r = g >> 3;
            int c = g & 7;
            cpa16(base + AT_BYTES + r * ROWB + c * 16,
                  W_g + (size_t)r * (C_ * 2) + kb + c * 16);
        }
        cpa_commit();
    };

    issue_stage(0, 0);
    issue_stage(1, 1);

    const int l15 = lane & 15;
    const int l7  = lane & 7;
    const int b_rowadd = ((lane >> 4) & 1) * 8 + l7;
    const int b_koff   = ((lane >> 3) & 1) * 16;

    for (int kt = 0; kt < NKT; kt++) {
        if (kt == NKT - 1) cpa_wait0(); else cpa_wait1();
        __syncthreads();
        if (kt + 2 < NKT) issue_stage(kt + 2, (kt + 2) % NSTAGE);

        const uint32_t base = sb + (kt % NSTAGE) * STAGEB;
        const uint32_t ah = base;
        const uint32_t bw = base + AT_BYTES;

#pragma unroll
        for (int ks = 0; ks < 4; ks++) {          // 4 x K16 within 64-chunk
            uint32_t af[4][4];
            uint32_t bf[4][2];
            const uint32_t arow = (warp_m + l15) * ROWB + ks * 32 + (lane >> 4) * 16;
#pragma unroll
            for (int mt = 0; mt < 4; mt++)
                ldsm_x4(af[mt][0], af[mt][1], af[mt][2], af[mt][3],
                        ah + arow + mt * (16 * ROWB));
#pragma unroll
            for (int p = 0; p < 2; p++) {
                uint32_t addr = bw + (warp_n + p * 16 + b_rowadd) * ROWB + ks * 32 + b_koff;
                ldsm_x4(bf[2*p][0], bf[2*p][1], bf[2*p+1][0], bf[2*p+1][1], addr);
            }
#pragma unroll
            for (int mt = 0; mt < 4; mt++)
#pragma unroll
                for (int nt = 0; nt < 4; nt++)
                    mma16816(acc[mt][nt][0], acc[mt][nt][1], acc[mt][nt][2], acc[mt][nt][3],
                             af[mt][0], af[mt][1], af[mt][2], af[mt][3],
                             bf[nt][0], bf[nt][1]);
        }
    }

    // ---- epilogue: fp16 half2 stores direct to global
    const int rbase = m0 + warp_m + (lane >> 2);
    const int cbase = n0 + warp_n + (lane & 3) * 2;
#pragma unroll
    for (int mt = 0; mt < 4; mt++) {
#pragma unroll
        for (int nt = 0; nt < 4; nt++) {
            float v0 = acc[mt][nt][0], v1 = acc[mt][nt][1];
            float v2 = acc[mt][nt][2], v3 = acc[mt][nt][3];
            if (which == 2) {
                v0 = 1.0f / (1.0f + __expf(-v0));
                v1 = 1.0f / (1.0f + __expf(-v1));
                v2 = 1.0f / (1.0f + __expf(-v2));
                v3 = 1.0f / (1.0f + __expf(-v3));
            }
            size_t r0 = (size_t)(rbase + mt * 16) * C_ + cbase + nt * 8;
            size_t r1 = r0 + 8 * C_;
            *reinterpret_cast<__half2*>(&Cout[r0]) =
                __halves2half2(__float2half_rn(v0), __float2half_rn(v1));
            *reinterpret_cast<__half2*>(&Cout[r1]) =
                __halves2half2(__float2half_rn(v2), __float2half_rn(v3));
        }
    }
}

// ---------------------------------------------------------------------------
// K3a: chunk-local WKV state summaries (A, B, P) — 32 chunks x 8192 channels.
// ---------------------------------------------------------------------------
__global__ __launch_bounds__(256)
void wkv_passA(const float* __restrict__ time_decay)
{
    const int tid = blockIdx.x * blockDim.x + threadIdx.x;  // 0..262143
    const int bc = tid & (BC_ - 1);
    const int j  = tid >> 13;
    const int c  = bc & (C_ - 1);
    const int b  = bc >> 10;

    const float w = -expf(time_decay[c]);
    float aa = 0.0f, bb = 0.0f, pp = -1e30f;

    const int base = (b * T_ + j * CL) * C_ + c;
#pragma unroll 4
    for (int i = 0; i < CL; i++) {
        float kt = __half2float(g_k16[base + i * C_]);
        float vt = __half2float(g_v16[base + i * C_]);
        float ww2 = pp + w;
        float d2  = ww2 - kt;
        float es  = __expf(-fabsf(d2));
        float e1  = (d2 >= 0.0f) ? 1.0f : es;
        float e2  = (d2 >= 0.0f) ? es : 1.0f;
        aa = e1 * aa + e2 * vt;
        bb = e1 * bb + e2;
        pp = fmaxf(ww2, kt);
    }
    g_chA[j][bc] = aa;
    g_chB[j][bc] = bb;
    g_chP[j][bc] = pp;
}

// ---------------------------------------------------------------------------
// K3b: serial compose over 32 chunk summaries -> incoming state per chunk.
// ---------------------------------------------------------------------------
__global__ __launch_bounds__(256)
void wkv_passB(const float* __restrict__ aa_init,
               const float* __restrict__ bb_init,
               const float* __restrict__ pp_init,
               const float* __restrict__ time_decay)
{
    const int bc = blockIdx.x * blockDim.x + threadIdx.x;  // 0..8191
    const int c  = bc & (C_ - 1);

    float aa = aa_init[bc], bb = bb_init[bc], pp = pp_init[bc];
    const float Lw = (float)CL * (-expf(time_decay[c]));

#pragma unroll
    for (int j = 0; j < NCH; j++) {
        g_inA[j][bc] = aa;
        g_inB[j][bc] = bb;
        g_inP[j][bc] = pp;
        float q  = pp + Lw;
        float Pj = g_chP[j][bc];
        float Aj = g_chA[j][bc];
        float Bj = g_chB[j][bc];
        float Pn = fmaxf(q, Pj);
        float e1 = __expf(q - Pn);
        float e2 = __expf(Pj - Pn);
        aa = e1 * aa + e2 * Aj;
        bb = e1 * bb + e2 * Bj;
        pp = Pn;
    }
}

// ---------------------------------------------------------------------------
// K3c: replay each chunk with its incoming state; emit partial ysum + ylast.
// ---------------------------------------------------------------------------
__global__ __launch_bounds__(256)
void wkv_passC(const float* __restrict__ time_decay,
               const float* __restrict__ time_first)
{
    const int tid = blockIdx.x * blockDim.x + threadIdx.x;  // 0..262143
    const int bc = tid & (BC_ - 1);
    const int j  = tid >> 13;
    const int c  = bc & (C_ - 1);
    const int b  = bc >> 10;

    const float w = -expf(time_decay[c]);
    const float u = time_first[c];

    float aa = g_inA[j][bc];
    float bb = g_inB[j][bc];
    float pp = g_inP[j][bc];

    float ysum = 0.0f;
    float y = 0.0f;

    const int base = (b * T_ + j * CL) * C_ + c;
#pragma unroll 4
    for (int i = 0; i < CL; i++) {
        float kt = __half2float(g_k16[base + i * C_]);
        float vt = __half2float(g_v16[base + i * C_]);
        float rt = __half2float(g_r16[base + i * C_]);
        float ww = u + kt;
        float d  = pp - ww;
        float es = __expf(-fabsf(d));
        float e1 = (d >= 0.0f) ? 1.0f : es;
        float e2 = (d >= 0.0f) ? es : 1.0f;
        y = rt * __fdividef(e1 * aa + e2 * vt, e1 * bb + e2);
        ysum += y;
        float ww2 = pp + w;
        float d2  = ww2 - kt;
        float es2 = __expf(-fabsf(d2));
        float e1b = (d2 >= 0.0f) ? 1.0f : es2;
        float e2b = (d2 >= 0.0f) ? es2 : 1.0f;
        aa = e1b * aa + e2b * vt;
        bb = e1b * bb + e2b;
        pp = fmaxf(ww2, kt);
    }
    g_psum[j][bc] = ysum;
    if (j == NCH - 1) g_ylast[bc] = y;
}

// ---------------------------------------------------------------------------
// K3d: reduce partials -> z = 0.5*(ylast + mean)
// ---------------------------------------------------------------------------
__global__ __launch_bounds__(256)
void wkv_reduce()
{
    const int bc = blockIdx.x * blockDim.x + threadIdx.x;  // 0..8191
    float s = 0.0f;
#pragma unroll
    for (int j = 0; j < NCH; j++) s += g_psum[j][bc];
    g_z[bc] = 0.5f * (g_ylast[bc] + s * (1.0f / (float)T_));
}

// ---------------------------------------------------------------------------
// K4: tiny output GEMM hx[b,d] = sum_c z[b,c] * Wo[d,c]; out = stack([hx,hx])
// ---------------------------------------------------------------------------
__global__ __launch_bounds__(256)
void final_proj_kernel(const float* __restrict__ Wo,
                       float* __restrict__ out)
{
    int gw   = (blockIdx.x * blockDim.x + threadIdx.x) >> 5;
    int lane = threadIdx.x & 31;
    if (gw >= BC_) return;
    int b = gw >> 10;
    int d = gw & (C_ - 1);

    const float* z  = g_z + b * C_;
    const float* wr = Wo + (size_t)d * C_;
    float s = 0.0f;
#pragma unroll 8
    for (int c = lane; c < C_; c += 32)
        s = fmaf(z[c], wr[c], s);
#pragma unroll
    for (int o = 16; o > 0; o >>= 1)
        s += __shfl_xor_sync(0xFFFFFFFFu, s, o);
    if (lane == 0) {
        out[b * C_ + d]       = s;
        out[BC_ + b * C_ + d] = s;
    }
}

// ---------------------------------------------------------------------------
extern "C" void kernel_launch(void* const* d_in, const int* in_sizes, int n_in,
                              void* d_out, int out_size)
{
    const int*   tok  = (const int*)  d_in[0];
    const float* xx   = (const float*)d_in[1];
    const float* aa   = (const float*)d_in[2];
    const float* bb   = (const float*)d_in[3];
    const float* pp   = (const float*)d_in[4];
    const float* emb  = (const float*)d_in[5];
    const float* tmk  = (const float*)d_in[6];
    const float* tmv  = (const float*)d_in[7];
    const float* tmr  = (const float*)d_in[8];
    const float* tdec = (const float*)d_in[9];
    const float* tfir = (const float*)d_in[10];
    const float* Wk   = (const float*)d_in[11];
    const float* Wv   = (const float*)d_in[12];
    const float* Wr   = (const float*)d_in[13];
    const float* Wo   = (const float*)d_in[14];
    float* out = (float*)d_out;

    cudaFuncSetAttribute(gemm_mma_kernel,
                         cudaFuncAttributeMaxDynamicSharedMemorySize, GEMM_SMEM);

    dim3 wgrid(C_ * C_ / 256, 3);
    conv_w_kernel<<<wgrid, 256>>>(Wk, Wv, Wr);

    embed_mix_kernel<<<BTC / 4 / 256, 256>>>(tok, xx, emb, tmk, tmv, tmr);

    dim3 ggrid(C_ / BN, M_ / BM, 3);   // (8, 128, 3)
    gemm_mma_kernel<<<ggrid, 256, GEMM_SMEM>>>();

    wkv_passA<<<(NCH * BC_) / 256, 256>>>(tdec);
    wkv_passB<<<BC_ / 256, 256>>>(aa, bb, pp, tdec);
    wkv_passC<<<(NCH * BC_) / 256, 256>>>(tdec, tfir);
    wkv_reduce<<<BC_ / 256, 256>>>();

    final_proj_kernel<<<(BC_ * 32) / 256, 256>>>(Wo, out);
}